// round 1
// baseline (speedup 1.0000x reference)
#include <cuda_runtime.h>
#include <cuda_bf16.h>
#include <math.h>

// Problem dims
#define BB 2
#define LL 2048
#define DD 512
#define NHH 8
#define NLL 4
#define DMM 2048
#define VV 32000
#define HDD 64
#define MM (BB*LL)          // 4096 rows

// ---------------- scratch (device globals; no allocations allowed) ----------
__device__ float g_h  [MM*DD];        // residual stream
__device__ float g_a  [MM*DD];        // LN output
__device__ float g_o  [MM*DD];        // attention output
__device__ float g_big[MM*DMM];       // qkv (4096x1536) / mlp hidden (4096x2048)

// ---------------- embedding -------------------------------------------------
__global__ void embed_kernel(const int* __restrict__ x,
                             const float* __restrict__ tok,
                             const float* __restrict__ pos,
                             float* __restrict__ h)
{
    int i = blockIdx.x * blockDim.x + threadIdx.x;   // over M*D
    int d  = i & (DD-1);
    int bl = i / DD;
    int l  = bl & (LL-1);
    h[i] = tok[(size_t)x[bl]*DD + d] + pos[l*DD + d];
}

// ---------------- layernorm (one block per row, D=512) ----------------------
__global__ __launch_bounds__(256) void layernorm_kernel(
    const float* __restrict__ x, const float* __restrict__ g,
    const float* __restrict__ b, float* __restrict__ y)
{
    __shared__ float red[16];
    __shared__ float stats[2];
    int row = blockIdx.x;
    int tid = threadIdx.x;
    const float2* xr = (const float2*)(x + (size_t)row*DD);
    float2 v = xr[tid];
    float s = v.x + v.y;
    float q = v.x*v.x + v.y*v.y;
    #pragma unroll
    for (int o = 16; o; o >>= 1) {
        s += __shfl_down_sync(0xffffffffu, s, o);
        q += __shfl_down_sync(0xffffffffu, q, o);
    }
    int w = tid >> 5;
    if ((tid & 31) == 0) { red[w] = s; red[w+8] = q; }
    __syncthreads();
    if (tid < 32) {
        s = (tid < 8) ? red[tid]   : 0.f;
        q = (tid < 8) ? red[tid+8] : 0.f;
        #pragma unroll
        for (int o = 4; o; o >>= 1) {
            s += __shfl_down_sync(0xffffffffu, s, o);
            q += __shfl_down_sync(0xffffffffu, q, o);
        }
        if (tid == 0) {
            float mu  = s * (1.0f/DD);
            float var = q * (1.0f/DD) - mu*mu;
            stats[0] = mu;
            stats[1] = rsqrtf(var + 1e-5f);
        }
    }
    __syncthreads();
    float mu = stats[0], inv = stats[1];
    float2 gg = ((const float2*)g)[tid];
    float2 bb = ((const float2*)b)[tid];
    float2 out;
    out.x = (v.x - mu)*inv*gg.x + bb.x;
    out.y = (v.y - mu)*inv*gg.y + bb.y;
    ((float2*)(y + (size_t)row*DD))[tid] = out;
}

// ---------------- SGEMM 128x128x16, 256 threads, 8x8 micro-tile -------------
// fuse: 0 = +bias, 1 = gelu(+bias), 2 = +bias+residual, 3 = plain (no bias)
#define BM 128
#define BN 128
#define BK 16
#define TM 8
#define TN 8

__global__ __launch_bounds__(256) void sgemm_kernel(
    const float* __restrict__ A, const float* __restrict__ Bw,
    const float* __restrict__ bias, const float* __restrict__ res,
    float* __restrict__ C, int Md, int Nd, int Kd, int fuse)
{
    __shared__ float As[BK][BM];
    __shared__ float Bs[BK][BN];

    int bx = blockIdx.x;   // N tile
    int by = blockIdx.y;   // M tile
    int tid = threadIdx.x;
    int tx = tid & 15;
    int ty = tid >> 4;

    const float* Aptr = A  + (size_t)by*BM*Kd;
    const float* Bptr = Bw + (size_t)bx*BN;

    float acc[TM][TN];
    #pragma unroll
    for (int i = 0; i < TM; i++)
        #pragma unroll
        for (int j = 0; j < TN; j++) acc[i][j] = 0.f;

    for (int k0 = 0; k0 < Kd; k0 += BK) {
        // A tile: 128x16 = 512 float4
        #pragma unroll
        for (int it = 0; it < 2; it++) {
            int id = tid + it*256;
            int r  = id >> 2;
            int c4 = (id & 3) << 2;
            float4 v = *(const float4*)(Aptr + (size_t)r*Kd + k0 + c4);
            As[c4+0][r] = v.x; As[c4+1][r] = v.y;
            As[c4+2][r] = v.z; As[c4+3][r] = v.w;
        }
        // B tile: 16x128 = 512 float4
        #pragma unroll
        for (int it = 0; it < 2; it++) {
            int id = tid + it*256;
            int r  = id >> 5;
            int c  = (id & 31) << 2;
            float4 v = *(const float4*)(Bptr + (size_t)(k0 + r)*Nd + c);
            *(float4*)(&Bs[r][c]) = v;
        }
        __syncthreads();
        #pragma unroll
        for (int kk = 0; kk < BK; kk++) {
            float ra[TM], rb[TN];
            #pragma unroll
            for (int i = 0; i < TM; i++) ra[i] = As[kk][ty*TM + i];
            #pragma unroll
            for (int j = 0; j < TN; j++) rb[j] = Bs[kk][tx*TN + j];
            #pragma unroll
            for (int i = 0; i < TM; i++)
                #pragma unroll
                for (int j = 0; j < TN; j++)
                    acc[i][j] += ra[i] * rb[j];
        }
        __syncthreads();
    }

    int row0 = by*BM + ty*TM;
    int col0 = bx*BN + tx*TN;
    #pragma unroll
    for (int i = 0; i < TM; i++) {
        int row = row0 + i;
        #pragma unroll
        for (int j = 0; j < TN; j++) {
            int col = col0 + j;
            float v = acc[i][j];
            if (fuse != 3) v += bias[col];
            if (fuse == 1) v = 0.5f * v * (1.0f + erff(v * 0.7071067811865475f));
            if (fuse == 2) v += res[(size_t)row*Nd + col];
            C[(size_t)row*Nd + col] = v;
        }
    }
}

// ---------------- flash-style causal attention ------------------------------
// one block: 64 queries of one (b,h); streams 64-key tiles; O in registers.
#define AQ 64
#define AK 64
#define QP 68            // padded row stride for Q/K/V tiles
#define SP 65            // padded row stride for score tile
#define ATTN_SMEM ((3*AQ*QP + AQ*SP + 3*AQ) * 4)

__global__ __launch_bounds__(256) void attn_kernel(
    const float* __restrict__ qkv, float* __restrict__ o)
{
    extern __shared__ float sm[];
    float* Qs   = sm;                  // 64 x 68
    float* Ks   = Qs + AQ*QP;          // 64 x 68
    float* Vs   = Ks + AQ*QP;          // 64 x 68
    float* S    = Vs + AQ*QP;          // 64 x 65
    float* mrow = S + AQ*SP;           // 64
    float* lrow = mrow + AQ;           // 64
    float* arow = lrow + AQ;           // 64

    int q0 = blockIdx.x * AQ;
    int h  = blockIdx.y;
    int b  = blockIdx.z;
    const float* base = qkv + (size_t)b * LL * (3*DD);
    int qoff = h*HDD;
    int koff = DD + h*HDD;
    int voff = 2*DD + h*HDD;

    int tid = threadIdx.x;
    int tx = tid & 15;
    int ty = tid >> 4;

    // load Q tile (64x64): 1024 float4, 4 per thread
    #pragma unroll
    for (int it = 0; it < 4; it++) {
        int id = tid + it*256;
        int r  = id >> 4;
        int c  = (id & 15) << 2;
        *(float4*)&Qs[r*QP + c] =
            *(const float4*)(base + (size_t)(q0 + r)*(3*DD) + qoff + c);
    }
    if (tid < AQ) { mrow[tid] = -1e30f; lrow[tid] = 0.f; }

    float oacc[4][4];
    #pragma unroll
    for (int i = 0; i < 4; i++)
        #pragma unroll
        for (int j = 0; j < 4; j++) oacc[i][j] = 0.f;

    int nk = q0 + AQ;
    for (int k0 = 0; k0 < nk; k0 += AK) {
        __syncthreads();   // protects Ks/Vs reuse + first-iter Q/init
        #pragma unroll
        for (int it = 0; it < 4; it++) {
            int id = tid + it*256;
            int r  = id >> 4;
            int c  = (id & 15) << 2;
            const float* rowp = base + (size_t)(k0 + r)*(3*DD);
            *(float4*)&Ks[r*QP + c] = *(const float4*)(rowp + koff + c);
            *(float4*)&Vs[r*QP + c] = *(const float4*)(rowp + voff + c);
        }
        __syncthreads();

        // S = scale * Q K^T with causal mask
        float sacc[4][4];
        #pragma unroll
        for (int i = 0; i < 4; i++)
            #pragma unroll
            for (int j = 0; j < 4; j++) sacc[i][j] = 0.f;

        #pragma unroll
        for (int d0 = 0; d0 < HDD; d0 += 4) {
            float4 qv[4], kv[4];
            #pragma unroll
            for (int i = 0; i < 4; i++) qv[i] = *(float4*)&Qs[(ty*4+i)*QP + d0];
            #pragma unroll
            for (int j = 0; j < 4; j++) kv[j] = *(float4*)&Ks[(tx*4+j)*QP + d0];
            #pragma unroll
            for (int i = 0; i < 4; i++)
                #pragma unroll
                for (int j = 0; j < 4; j++)
                    sacc[i][j] += qv[i].x*kv[j].x + qv[i].y*kv[j].y
                                + qv[i].z*kv[j].z + qv[i].w*kv[j].w;
        }
        #pragma unroll
        for (int i = 0; i < 4; i++) {
            int qi = ty*4 + i;
            #pragma unroll
            for (int j = 0; j < 4; j++) {
                int kj = tx*4 + j;
                float s = sacc[i][j] * 0.125f;      // 1/sqrt(64)
                if (k0 + kj > q0 + qi) s = -1e30f;  // causal mask
                S[qi*SP + kj] = s;
            }
        }
        __syncthreads();

        // online softmax per query row (threads 0..63)
        if (tid < AQ) {
            float mx = -1e30f;
            #pragma unroll 8
            for (int j = 0; j < AK; j++) mx = fmaxf(mx, S[tid*SP + j]);
            float mold = mrow[tid];
            float mnew = fmaxf(mold, mx);
            float alpha = __expf(mold - mnew);      // 0 on first tile (mold=-1e30)
            float sum = 0.f;
            #pragma unroll 8
            for (int j = 0; j < AK; j++) {
                float p = __expf(S[tid*SP + j] - mnew);
                S[tid*SP + j] = p;
                sum += p;
            }
            lrow[tid] = lrow[tid]*alpha + sum;
            mrow[tid] = mnew;
            arow[tid] = alpha;
        }
        __syncthreads();

        // O = O*alpha + P @ V
        float al[4];
        #pragma unroll
        for (int i = 0; i < 4; i++) al[i] = arow[ty*4 + i];
        #pragma unroll
        for (int i = 0; i < 4; i++)
            #pragma unroll
            for (int j = 0; j < 4; j++) oacc[i][j] *= al[i];

        #pragma unroll 4
        for (int kk = 0; kk < AK; kk++) {
            float pa[4];
            #pragma unroll
            for (int i = 0; i < 4; i++) pa[i] = S[(ty*4+i)*SP + kk];
            float4 vb = *(float4*)&Vs[kk*QP + tx*4];
            #pragma unroll
            for (int i = 0; i < 4; i++) {
                oacc[i][0] += pa[i]*vb.x;
                oacc[i][1] += pa[i]*vb.y;
                oacc[i][2] += pa[i]*vb.z;
                oacc[i][3] += pa[i]*vb.w;
            }
        }
    }
    __syncthreads();

    // write O / l
    #pragma unroll
    for (int i = 0; i < 4; i++) {
        int qi = ty*4 + i;
        float invl = 1.0f / lrow[qi];
        float4 out;
        out.x = oacc[i][0]*invl; out.y = oacc[i][1]*invl;
        out.z = oacc[i][2]*invl; out.w = oacc[i][3]*invl;
        size_t m = (size_t)b*LL + q0 + qi;
        *(float4*)(o + m*DD + h*HDD + tx*4) = out;
    }
}

// ---------------- launcher ---------------------------------------------------
extern "C" void kernel_launch(void* const* d_in, const int* in_sizes, int n_in,
                              void* d_out, int out_size)
{
    const int*   x     = (const int*)  d_in[0];
    const float* tok   = (const float*)d_in[1];
    const float* pos   = (const float*)d_in[2];
    const float* ln1g  = (const float*)d_in[3];
    const float* ln1b  = (const float*)d_in[4];
    const float* qkvw  = (const float*)d_in[5];
    const float* qkvb  = (const float*)d_in[6];
    const float* outw  = (const float*)d_in[7];
    const float* outb  = (const float*)d_in[8];
    const float* ln2g  = (const float*)d_in[9];
    const float* ln2b  = (const float*)d_in[10];
    const float* w1    = (const float*)d_in[11];
    const float* b1    = (const float*)d_in[12];
    const float* w2    = (const float*)d_in[13];
    const float* b2    = (const float*)d_in[14];
    const float* lnfg  = (const float*)d_in[15];
    const float* lnfb  = (const float*)d_in[16];
    const float* headw = (const float*)d_in[17];
    float* out = (float*)d_out;

    float *h, *a, *o, *big;
    cudaGetSymbolAddress((void**)&h,   g_h);
    cudaGetSymbolAddress((void**)&a,   g_a);
    cudaGetSymbolAddress((void**)&o,   g_o);
    cudaGetSymbolAddress((void**)&big, g_big);

    cudaFuncSetAttribute(attn_kernel,
        cudaFuncAttributeMaxDynamicSharedMemorySize, ATTN_SMEM);

    embed_kernel<<<(MM*DD)/256, 256>>>(x, tok, pos, h);

    for (int i = 0; i < NLL; i++) {
        layernorm_kernel<<<MM, 256>>>(h, ln1g + i*DD, ln1b + i*DD, a);
        sgemm_kernel<<<dim3((3*DD)/BN, MM/BM), 256>>>(
            a, qkvw + (size_t)i*DD*3*DD, qkvb + (size_t)i*3*DD,
            nullptr, big, MM, 3*DD, DD, 0);
        attn_kernel<<<dim3(LL/AQ, NHH, BB), 256, ATTN_SMEM>>>(big, o);
        sgemm_kernel<<<dim3(DD/BN, MM/BM), 256>>>(
            o, outw + (size_t)i*DD*DD, outb + (size_t)i*DD,
            h, h, MM, DD, DD, 2);
        layernorm_kernel<<<MM, 256>>>(h, ln2g + i*DD, ln2b + i*DD, a);
        sgemm_kernel<<<dim3(DMM/BN, MM/BM), 256>>>(
            a, w1 + (size_t)i*DD*DMM, b1 + (size_t)i*DMM,
            nullptr, big, MM, DMM, DD, 1);
        sgemm_kernel<<<dim3(DD/BN, MM/BM), 256>>>(
            big, w2 + (size_t)i*DMM*DD, b2 + (size_t)i*DD,
            h, h, MM, DD, DMM, 2);
    }

    layernorm_kernel<<<MM, 256>>>(h, lnfg, lnfb, a);
    sgemm_kernel<<<dim3(VV/BN, MM/BM), 256>>>(
        a, headw, nullptr, nullptr, out, MM, VV, DD, 3);
}

// round 7
// speedup vs baseline: 1.7450x; 1.7450x over previous
#include <cuda_runtime.h>
#include <cuda_bf16.h>
#include <math.h>
#include <stdint.h>

typedef __nv_bfloat16 bf16;

// Problem dims
#define BB 2
#define LL 2048
#define DD 512
#define NHH 8
#define NLL 4
#define DMM 2048
#define VV 32000
#define HDD 64
#define MM (BB*LL)          // 4096 rows

// ---------------- PTX helpers ------------------------------------------------
__device__ __forceinline__ uint32_t smem_u32(const void* p) {
    uint32_t a;
    asm("{ .reg .u64 t; cvta.to.shared.u64 t, %1; cvt.u32.u64 %0, t; }"
        : "=r"(a) : "l"(p));
    return a;
}

#define LDSM_X4(r0,r1,r2,r3,addr) \
    asm volatile("ldmatrix.sync.aligned.m8n8.x4.shared.b16 {%0,%1,%2,%3}, [%4];" \
        : "=r"(r0), "=r"(r1), "=r"(r2), "=r"(r3) : "r"(addr))
#define LDSM_X2(r0,r1,addr) \
    asm volatile("ldmatrix.sync.aligned.m8n8.x2.shared.b16 {%0,%1}, [%2];" \
        : "=r"(r0), "=r"(r1) : "r"(addr))
#define MMA16816(d, a, b) \
    asm volatile("mma.sync.aligned.m16n8k16.row.col.f32.bf16.bf16.f32 " \
        "{%0,%1,%2,%3}, {%4,%5,%6,%7}, {%8,%9}, {%0,%1,%2,%3};" \
        : "+f"((d)[0]), "+f"((d)[1]), "+f"((d)[2]), "+f"((d)[3]) \
        : "r"((a)[0]), "r"((a)[1]), "r"((a)[2]), "r"((a)[3]), \
          "r"((b)[0]), "r"((b)[1]))

// ---------------- scratch (device globals) -----------------------------------
__device__ float g_h  [MM*DD];
__device__ float g_a  [MM*DD];
__device__ float g_o  [MM*DD];
__device__ float g_big[MM*DMM];
__device__ bf16  g_xh [MM*DMM];
__device__ bf16  g_xl [MM*DMM];

// transposed+split weights [N,K] bf16
#define W_QKV0 0
#define W_OUT0 3145728
#define W_W10  4194304
#define W_W20  8388608
#define W_HEAD 12582912
#define WTOT   28966912
__device__ bf16 g_wh[WTOT];
__device__ bf16 g_wl[WTOT];

// ---------------- embedding --------------------------------------------------
__global__ void embed_kernel(const int* __restrict__ x,
                             const float* __restrict__ tok,
                             const float* __restrict__ pos,
                             float* __restrict__ h)
{
    int i = blockIdx.x * blockDim.x + threadIdx.x;
    int d  = i & (DD-1);
    int bl = i / DD;
    int l  = bl & (LL-1);
    h[i] = tok[(size_t)x[bl]*DD + d] + pos[l*DD + d];
}

// ---------------- layernorm --------------------------------------------------
__global__ __launch_bounds__(256) void layernorm_kernel(
    const float* __restrict__ x, const float* __restrict__ g,
    const float* __restrict__ b, float* __restrict__ y)
{
    __shared__ float red[16];
    __shared__ float stats[2];
    int row = blockIdx.x;
    int tid = threadIdx.x;
    const float2* xr = (const float2*)(x + (size_t)row*DD);
    float2 v = xr[tid];
    float s = v.x + v.y;
    float q = v.x*v.x + v.y*v.y;
    #pragma unroll
    for (int o = 16; o; o >>= 1) {
        s += __shfl_down_sync(0xffffffffu, s, o);
        q += __shfl_down_sync(0xffffffffu, q, o);
    }
    int w = tid >> 5;
    if ((tid & 31) == 0) { red[w] = s; red[w+8] = q; }
    __syncthreads();
    if (tid < 32) {
        s = (tid < 8) ? red[tid]   : 0.f;
        q = (tid < 8) ? red[tid+8] : 0.f;
        #pragma unroll
        for (int o = 4; o; o >>= 1) {
            s += __shfl_down_sync(0xffffffffu, s, o);
            q += __shfl_down_sync(0xffffffffu, q, o);
        }
        if (tid == 0) {
            float mu  = s * (1.0f/DD);
            float var = q * (1.0f/DD) - mu*mu;
            stats[0] = mu;
            stats[1] = rsqrtf(var + 1e-5f);
        }
    }
    __syncthreads();
    float mu = stats[0], inv = stats[1];
    float2 gg = ((const float2*)g)[tid];
    float2 bb = ((const float2*)b)[tid];
    float2 out;
    out.x = (v.x - mu)*inv*gg.x + bb.x;
    out.y = (v.y - mu)*inv*gg.y + bb.y;
    ((float2*)(y + (size_t)row*DD))[tid] = out;
}

// ---------------- fp32 -> bf16 hi/lo split -----------------------------------
__global__ void split_kernel(const float* __restrict__ in,
                             bf16* __restrict__ hi, bf16* __restrict__ lo)
{
    int i = (blockIdx.x * blockDim.x + threadIdx.x) * 4;
    float4 v = *(const float4*)(in + i);
    bf16 h0 = __float2bfloat16(v.x), h1 = __float2bfloat16(v.y);
    bf16 h2 = __float2bfloat16(v.z), h3 = __float2bfloat16(v.w);
    bf16 l0 = __float2bfloat16(v.x - __bfloat162float(h0));
    bf16 l1 = __float2bfloat16(v.y - __bfloat162float(h1));
    bf16 l2 = __float2bfloat16(v.z - __bfloat162float(h2));
    bf16 l3 = __float2bfloat16(v.w - __bfloat162float(h3));
    *(uint2*)(hi + i) = make_uint2(
        (uint32_t)__bfloat16_as_ushort(h0) | ((uint32_t)__bfloat16_as_ushort(h1) << 16),
        (uint32_t)__bfloat16_as_ushort(h2) | ((uint32_t)__bfloat16_as_ushort(h3) << 16));
    *(uint2*)(lo + i) = make_uint2(
        (uint32_t)__bfloat16_as_ushort(l0) | ((uint32_t)__bfloat16_as_ushort(l1) << 16),
        (uint32_t)__bfloat16_as_ushort(l2) | ((uint32_t)__bfloat16_as_ushort(l3) << 16));
}

// ---------------- weight transpose+split: in [K,N] -> out [N,K] hi/lo --------
__global__ __launch_bounds__(256) void tsplit_kernel(
    const float* __restrict__ in, bf16* __restrict__ hi, bf16* __restrict__ lo,
    int K, int N)
{
    __shared__ float t[32][33];
    int n0 = blockIdx.x * 32, k0 = blockIdx.y * 32;
    int tx = threadIdx.x, ty = threadIdx.y;
    #pragma unroll
    for (int i = ty; i < 32; i += 8)
        t[i][tx] = in[(size_t)(k0+i)*N + n0 + tx];
    __syncthreads();
    #pragma unroll
    for (int i = ty; i < 32; i += 8) {
        float v = t[tx][i];
        bf16 h = __float2bfloat16(v);
        bf16 l = __float2bfloat16(v - __bfloat162float(h));
        size_t o = (size_t)(n0+i)*K + k0 + tx;
        hi[o] = h; lo[o] = l;
    }
}

// ---------------- mma.sync bf16x3 GEMM 128x128, K-chunks of 64 ---------------
// A [M,K] row-major (hi/lo), B [N,K] row-major (hi/lo). C = A@B^T (+epilogue).
// fuse: 0=+bias, 1=gelu(+bias), 2=+bias+residual, 3=plain
#define TSTR 72   // smem row stride in bf16 elems (144B: conflict-free ldmatrix)

__global__ __launch_bounds__(256) void tcgemm(
    const bf16* __restrict__ Ah, const bf16* __restrict__ Al,
    const bf16* __restrict__ Bh, const bf16* __restrict__ Bl,
    const float* __restrict__ bias, const float* __restrict__ res,
    float* __restrict__ C, int Kd, int Nd, int fuse)
{
    __shared__ __align__(16) bf16 As[128*TSTR];
    __shared__ __align__(16) bf16 Bs[128*TSTR];
    uint32_t asb = smem_u32(As), bsb = smem_u32(Bs);

    int tid = threadIdx.x, lane = tid & 31, wid = tid >> 5;
    int m0w = (wid >> 2) * 64;      // warp M offset in tile
    int n0w = (wid & 3) * 32;       // warp N offset in tile
    int bn0  = blockIdx.x * 128;
    int row0 = blockIdx.y * 128;

    float acc[16][4];
    #pragma unroll
    for (int i = 0; i < 16; i++)
        #pragma unroll
        for (int j = 0; j < 4; j++) acc[i][j] = 0.f;

    int kseg  = Kd >> 6;
    int total = 3 * kseg;

    // per-thread load/store indices (4 float4 each for A and B per chunk)
    int lr[4], lc[4];
    #pragma unroll
    for (int p = 0; p < 4; p++) {
        int id = tid + (p << 8);
        lr[p] = id >> 3;            // row 0..127
        lc[p] = (id & 7) << 3;      // col elem 0..56 step 8
    }

    float4 pa[4], pb[4];

    // prefetch chunk 0 (seg 0: Ah, Bh; kk = 0)
    #pragma unroll
    for (int p = 0; p < 4; p++) {
        pa[p] = *(const float4*)(Ah + (size_t)(row0 + lr[p])*Kd + lc[p]);
        pb[p] = *(const float4*)(Bh + (size_t)(bn0 + lr[p])*Kd + lc[p]);
    }

    for (int c = 0; c < total; c++) {
        // commit prefetched chunk to smem
        #pragma unroll
        for (int p = 0; p < 4; p++) {
            *(float4*)(As + lr[p]*TSTR + lc[p]) = pa[p];
            *(float4*)(Bs + lr[p]*TSTR + lc[p]) = pb[p];
        }
        __syncthreads();

        // prefetch next chunk while computing
        if (c + 1 < total) {
            int cn  = c + 1;
            int seg = cn / kseg;
            int kk  = (cn - seg * kseg) << 6;
            const bf16* Asrc = (seg == 1) ? Al : Ah;
            const bf16* Bsrc = (seg == 2) ? Bl : Bh;
            #pragma unroll
            for (int p = 0; p < 4; p++) {
                pa[p] = *(const float4*)(Asrc + (size_t)(row0 + lr[p])*Kd + kk + lc[p]);
                pb[p] = *(const float4*)(Bsrc + (size_t)(bn0 + lr[p])*Kd + kk + lc[p]);
            }
        }

        // compute: 4 k16 steps over the 64-wide chunk
        #pragma unroll
        for (int ks = 0; ks < 4; ks++) {
            uint32_t af[4][4], bf[4][2];
            #pragma unroll
            for (int mt = 0; mt < 4; mt++) {
                uint32_t addr = asb +
                    (((m0w + mt*16 + (lane & 15)) * TSTR) +
                     ks*16 + ((lane >> 4) << 3)) * 2;
                LDSM_X4(af[mt][0], af[mt][1], af[mt][2], af[mt][3], addr);
            }
            #pragma unroll
            for (int nt = 0; nt < 4; nt++) {
                uint32_t addr = bsb +
                    (((n0w + nt*8 + (lane & 7)) * TSTR) +
                     ks*16 + (((lane >> 3) & 1) << 3)) * 2;
                LDSM_X2(bf[nt][0], bf[nt][1], addr);
            }
            #pragma unroll
            for (int mt = 0; mt < 4; mt++)
                #pragma unroll
                for (int nt = 0; nt < 4; nt++)
                    MMA16816(acc[mt*4 + nt], af[mt], bf[nt]);
        }
        __syncthreads();
    }

    // epilogue: each thread owns 2 rows x 2 cols per mma tile
    #pragma unroll
    for (int mt = 0; mt < 4; mt++) {
        int r0 = row0 + m0w + mt*16 + (lane >> 2);
        #pragma unroll
        for (int nt = 0; nt < 4; nt++) {
            int col = bn0 + n0w + nt*8 + ((lane & 3) << 1);
            float* dst0 = C + (size_t)r0*Nd + col;
            float* dst1 = dst0 + 8*(size_t)Nd;
            float2 v0 = make_float2(acc[mt*4+nt][0], acc[mt*4+nt][1]);
            float2 v1 = make_float2(acc[mt*4+nt][2], acc[mt*4+nt][3]);
            if (fuse != 3) {
                float2 bv = *(const float2*)(bias + col);
                v0.x += bv.x; v0.y += bv.y;
                v1.x += bv.x; v1.y += bv.y;
            }
            if (fuse == 1) {
                v0.x = 0.5f*v0.x*(1.0f + erff(v0.x*0.7071067811865475f));
                v0.y = 0.5f*v0.y*(1.0f + erff(v0.y*0.7071067811865475f));
                v1.x = 0.5f*v1.x*(1.0f + erff(v1.x*0.7071067811865475f));
                v1.y = 0.5f*v1.y*(1.0f + erff(v1.y*0.7071067811865475f));
            }
            if (fuse == 2) {
                float2 r0v = *(const float2*)(res + (size_t)r0*Nd + col);
                float2 r1v = *(const float2*)(res + (size_t)(r0+8)*Nd + col);
                v0.x += r0v.x; v0.y += r0v.y;
                v1.x += r1v.x; v1.y += r1v.y;
            }
            *(float2*)dst0 = v0;
            *(float2*)dst1 = v1;
        }
    }
}

// ---------------- flash-style causal attention (fp32) -------------------------
#define AQ 64
#define AK 64
#define QP 68
#define SP 65
#define ATTN_SMEM ((3*AQ*QP + AQ*SP + 3*AQ) * 4)

__global__ __launch_bounds__(256) void attn_kernel(
    const float* __restrict__ qkv, float* __restrict__ o)
{
    extern __shared__ float smf[];
    float* Qs   = smf;
    float* Ks   = Qs + AQ*QP;
    float* Vs   = Ks + AQ*QP;
    float* S    = Vs + AQ*QP;
    float* mrow = S + AQ*SP;
    float* lrow = mrow + AQ;
    float* arow = lrow + AQ;

    int q0 = blockIdx.x * AQ;
    int h  = blockIdx.y;
    int b  = blockIdx.z;
    const float* base = qkv + (size_t)b * LL * (3*DD);
    int qoff = h*HDD;
    int koff = DD + h*HDD;
    int voff = 2*DD + h*HDD;

    int tid = threadIdx.x;
    int tx = tid & 15;
    int ty = tid >> 4;

    #pragma unroll
    for (int it = 0; it < 4; it++) {
        int id = tid + it*256;
        int r  = id >> 4;
        int c  = (id & 15) << 2;
        *(float4*)&Qs[r*QP + c] =
            *(const float4*)(base + (size_t)(q0 + r)*(3*DD) + qoff + c);
    }
    if (tid < AQ) { mrow[tid] = -1e30f; lrow[tid] = 0.f; }

    float oacc[4][4];
    #pragma unroll
    for (int i = 0; i < 4; i++)
        #pragma unroll
        for (int j = 0; j < 4; j++) oacc[i][j] = 0.f;

    int nk = q0 + AQ;
    for (int k0 = 0; k0 < nk; k0 += AK) {
        __syncthreads();
        #pragma unroll
        for (int it = 0; it < 4; it++) {
            int id = tid + it*256;
            int r  = id >> 4;
            int c  = (id & 15) << 2;
            const float* rowp = base + (size_t)(k0 + r)*(3*DD);
            *(float4*)&Ks[r*QP + c] = *(const float4*)(rowp + koff + c);
            *(float4*)&Vs[r*QP + c] = *(const float4*)(rowp + voff + c);
        }
        __syncthreads();

        float sacc[4][4];
        #pragma unroll
        for (int i = 0; i < 4; i++)
            #pragma unroll
            for (int j = 0; j < 4; j++) sacc[i][j] = 0.f;

        #pragma unroll
        for (int d0 = 0; d0 < HDD; d0 += 4) {
            float4 qv[4], kv[4];
            #pragma unroll
            for (int i = 0; i < 4; i++) qv[i] = *(float4*)&Qs[(ty*4+i)*QP + d0];
            #pragma unroll
            for (int j = 0; j < 4; j++) kv[j] = *(float4*)&Ks[(tx*4+j)*QP + d0];
            #pragma unroll
            for (int i = 0; i < 4; i++)
                #pragma unroll
                for (int j = 0; j < 4; j++)
                    sacc[i][j] += qv[i].x*kv[j].x + qv[i].y*kv[j].y
                                + qv[i].z*kv[j].z + qv[i].w*kv[j].w;
        }
        #pragma unroll
        for (int i = 0; i < 4; i++) {
            int qi = ty*4 + i;
            #pragma unroll
            for (int j = 0; j < 4; j++) {
                int kj = tx*4 + j;
                float s = sacc[i][j] * 0.125f;
                if (k0 + kj > q0 + qi) s = -1e30f;
                S[qi*SP + kj] = s;
            }
        }
        __syncthreads();

        if (tid < AQ) {
            float mx = -1e30f;
            #pragma unroll 8
            for (int j = 0; j < AK; j++) mx = fmaxf(mx, S[tid*SP + j]);
            float mold = mrow[tid];
            float mnew = fmaxf(mold, mx);
            float alpha = __expf(mold - mnew);
            float sum = 0.f;
            #pragma unroll 8
            for (int j = 0; j < AK; j++) {
                float p = __expf(S[tid*SP + j] - mnew);
                S[tid*SP + j] = p;
                sum += p;
            }
            lrow[tid] = lrow[tid]*alpha + sum;
            mrow[tid] = mnew;
            arow[tid] = alpha;
        }
        __syncthreads();

        float al[4];
        #pragma unroll
        for (int i = 0; i < 4; i++) al[i] = arow[ty*4 + i];
        #pragma unroll
        for (int i = 0; i < 4; i++)
            #pragma unroll
            for (int j = 0; j < 4; j++) oacc[i][j] *= al[i];

        #pragma unroll 4
        for (int kk = 0; kk < AK; kk++) {
            float pa[4];
            #pragma unroll
            for (int i = 0; i < 4; i++) pa[i] = S[(ty*4+i)*SP + kk];
            float4 vb = *(float4*)&Vs[kk*QP + tx*4];
            #pragma unroll
            for (int i = 0; i < 4; i++) {
                oacc[i][0] += pa[i]*vb.x;
                oacc[i][1] += pa[i]*vb.y;
                oacc[i][2] += pa[i]*vb.z;
                oacc[i][3] += pa[i]*vb.w;
            }
        }
    }
    __syncthreads();

    #pragma unroll
    for (int i = 0; i < 4; i++) {
        int qi = ty*4 + i;
        float invl = 1.0f / lrow[qi];
        float4 out;
        out.x = oacc[i][0]*invl; out.y = oacc[i][1]*invl;
        out.z = oacc[i][2]*invl; out.w = oacc[i][3]*invl;
        size_t m = (size_t)b*LL + q0 + qi;
        *(float4*)(o + m*DD + h*HDD + tx*4) = out;
    }
}

// ---------------- launcher ----------------------------------------------------
extern "C" void kernel_launch(void* const* d_in, const int* in_sizes, int n_in,
                              void* d_out, int out_size)
{
    const int*   x     = (const int*)  d_in[0];
    const float* tok   = (const float*)d_in[1];
    const float* pos   = (const float*)d_in[2];
    const float* ln1g  = (const float*)d_in[3];
    const float* ln1b  = (const float*)d_in[4];
    const float* qkvw  = (const float*)d_in[5];
    const float* qkvb  = (const float*)d_in[6];
    const float* outw  = (const float*)d_in[7];
    const float* outb  = (const float*)d_in[8];
    const float* ln2g  = (const float*)d_in[9];
    const float* ln2b  = (const float*)d_in[10];
    const float* w1    = (const float*)d_in[11];
    const float* b1    = (const float*)d_in[12];
    const float* w2    = (const float*)d_in[13];
    const float* b2    = (const float*)d_in[14];
    const float* lnfg  = (const float*)d_in[15];
    const float* lnfb  = (const float*)d_in[16];
    const float* headw = (const float*)d_in[17];
    float* out = (float*)d_out;

    float *h, *a, *o, *big;
    bf16 *xh, *xl, *wh, *wl;
    cudaGetSymbolAddress((void**)&h,   g_h);
    cudaGetSymbolAddress((void**)&a,   g_a);
    cudaGetSymbolAddress((void**)&o,   g_o);
    cudaGetSymbolAddress((void**)&big, g_big);
    cudaGetSymbolAddress((void**)&xh,  g_xh);
    cudaGetSymbolAddress((void**)&xl,  g_xl);
    cudaGetSymbolAddress((void**)&wh,  g_wh);
    cudaGetSymbolAddress((void**)&wl,  g_wl);

    cudaFuncSetAttribute(attn_kernel,
        cudaFuncAttributeMaxDynamicSharedMemorySize, ATTN_SMEM);

    // weight prep: transpose [K,N] -> [N,K] + bf16 hi/lo split
    dim3 tb(32, 8);
    for (int i = 0; i < NLL; i++) {
        tsplit_kernel<<<dim3(1536/32, 512/32), tb>>>(
            qkvw + (size_t)i*DD*3*DD, wh + W_QKV0 + (size_t)i*786432,
            wl + W_QKV0 + (size_t)i*786432, 512, 1536);
        tsplit_kernel<<<dim3(512/32, 512/32), tb>>>(
            outw + (size_t)i*DD*DD, wh + W_OUT0 + (size_t)i*262144,
            wl + W_OUT0 + (size_t)i*262144, 512, 512);
        tsplit_kernel<<<dim3(2048/32, 512/32), tb>>>(
            w1 + (size_t)i*DD*DMM, wh + W_W10 + (size_t)i*1048576,
            wl + W_W10 + (size_t)i*1048576, 512, 2048);
        tsplit_kernel<<<dim3(512/32, 2048/32), tb>>>(
            w2 + (size_t)i*DMM*DD, wh + W_W20 + (size_t)i*1048576,
            wl + W_W20 + (size_t)i*1048576, 2048, 512);
    }
    tsplit_kernel<<<dim3(32000/32, 512/32), tb>>>(
        headw, wh + W_HEAD, wl + W_HEAD, 512, 32000);

    embed_kernel<<<(MM*DD)/256, 256>>>(x, tok, pos, h);

    for (int i = 0; i < NLL; i++) {
        // attn block
        layernorm_kernel<<<MM, 256>>>(h, ln1g + i*DD, ln1b + i*DD, a);
        split_kernel<<<(MM*DD)/1024, 256>>>(a, xh, xl);
        tcgemm<<<dim3(1536/128, MM/128), 256>>>(
            xh, xl, wh + W_QKV0 + (size_t)i*786432, wl + W_QKV0 + (size_t)i*786432,
            qkvb + (size_t)i*3*DD, nullptr, big, 512, 1536, 0);
        attn_kernel<<<dim3(LL/AQ, NHH, BB), 256, ATTN_SMEM>>>(big, o);
        split_kernel<<<(MM*DD)/1024, 256>>>(o, xh, xl);
        tcgemm<<<dim3(512/128, MM/128), 256>>>(
            xh, xl, wh + W_OUT0 + (size_t)i*262144, wl + W_OUT0 + (size_t)i*262144,
            outb + (size_t)i*DD, h, h, 512, 512, 2);
        // mlp block
        layernorm_kernel<<<MM, 256>>>(h, ln2g + i*DD, ln2b + i*DD, a);
        split_kernel<<<(MM*DD)/1024, 256>>>(a, xh, xl);
        tcgemm<<<dim3(2048/128, MM/128), 256>>>(
            xh, xl, wh + W_W10 + (size_t)i*1048576, wl + W_W10 + (size_t)i*1048576,
            b1 + (size_t)i*DMM, nullptr, big, 512, 2048, 1);
        split_kernel<<<(MM*DMM)/1024, 256>>>(big, xh, xl);
        tcgemm<<<dim3(512/128, MM/128), 256>>>(
            xh, xl, wh + W_W20 + (size_t)i*1048576, wl + W_W20 + (size_t)i*1048576,
            b2 + (size_t)i*DD, h, h, 2048, 512, 2);
    }

    layernorm_kernel<<<MM, 256>>>(h, lnfg, lnfb, a);
    split_kernel<<<(MM*DD)/1024, 256>>>(a, xh, xl);
    tcgemm<<<dim3(VV/128, MM/128), 256>>>(
        xh, xl, wh + W_HEAD, wl + W_HEAD,
        nullptr, nullptr, out, 512, VV, 3);
}

// round 8
// speedup vs baseline: 2.5721x; 1.4739x over previous
#include <cuda_runtime.h>
#include <cuda_bf16.h>
#include <math.h>
#include <stdint.h>

typedef __nv_bfloat16 bf16;

// Problem dims
#define BB 2
#define LL 2048
#define DD 512
#define NHH 8
#define NLL 4
#define DMM 2048
#define VV 32000
#define HDD 64
#define MM (BB*LL)          // 4096 rows

// ---------------- PTX helpers ------------------------------------------------
__device__ __forceinline__ uint32_t smem_u32(const void* p) {
    uint32_t a;
    asm("{ .reg .u64 t; cvta.to.shared.u64 t, %1; cvt.u32.u64 %0, t; }"
        : "=r"(a) : "l"(p));
    return a;
}

#define LDSM_X4(r0,r1,r2,r3,addr) \
    asm volatile("ldmatrix.sync.aligned.m8n8.x4.shared.b16 {%0,%1,%2,%3}, [%4];" \
        : "=r"(r0), "=r"(r1), "=r"(r2), "=r"(r3) : "r"(addr))
#define LDSM_X4_T(r0,r1,r2,r3,addr) \
    asm volatile("ldmatrix.sync.aligned.m8n8.x4.trans.shared.b16 {%0,%1,%2,%3}, [%4];" \
        : "=r"(r0), "=r"(r1), "=r"(r2), "=r"(r3) : "r"(addr))
#define LDSM_X2(r0,r1,addr) \
    asm volatile("ldmatrix.sync.aligned.m8n8.x2.shared.b16 {%0,%1}, [%2];" \
        : "=r"(r0), "=r"(r1) : "r"(addr))
#define MMA16816(d, a, b) \
    asm volatile("mma.sync.aligned.m16n8k16.row.col.f32.bf16.bf16.f32 " \
        "{%0,%1,%2,%3}, {%4,%5,%6,%7}, {%8,%9}, {%0,%1,%2,%3};" \
        : "+f"((d)[0]), "+f"((d)[1]), "+f"((d)[2]), "+f"((d)[3]) \
        : "r"((a)[0]), "r"((a)[1]), "r"((a)[2]), "r"((a)[3]), \
          "r"((b)[0]), "r"((b)[1]))

// pack two fp32 into bf16x2 hi + residual-lo words
__device__ __forceinline__ void split2(float a, float b, uint32_t &h, uint32_t &l) {
    bf16 ha = __float2bfloat16(a), hb = __float2bfloat16(b);
    float ra = a - __bfloat162float(ha);
    float rb = b - __bfloat162float(hb);
    h = (uint32_t)__bfloat16_as_ushort(ha) |
        ((uint32_t)__bfloat16_as_ushort(hb) << 16);
    l = (uint32_t)__bfloat16_as_ushort(__float2bfloat16(ra)) |
        ((uint32_t)__bfloat16_as_ushort(__float2bfloat16(rb)) << 16);
}

// ---------------- scratch (device globals) -----------------------------------
__device__ float g_h  [MM*DD];        // residual stream
__device__ float g_big[MM*3*DD];      // qkv fp32
__device__ bf16  g_xh [MM*DD];        // activation hi (LN out / attn out)
__device__ bf16  g_xl [MM*DD];
__device__ bf16  g_mh [MM*DMM];       // mlp hidden hi/lo
__device__ bf16  g_ml [MM*DMM];

// transposed+split weights [N,K] bf16
#define W_QKV0 0
#define W_OUT0 3145728
#define W_W10  4194304
#define W_W20  8388608
#define W_HEAD 12582912
#define WTOT   28966912
__device__ bf16 g_wh[WTOT];
__device__ bf16 g_wl[WTOT];

// ---------------- embedding --------------------------------------------------
__global__ void embed_kernel(const int* __restrict__ x,
                             const float* __restrict__ tok,
                             const float* __restrict__ pos,
                             float* __restrict__ h)
{
    int i = blockIdx.x * blockDim.x + threadIdx.x;
    int d  = i & (DD-1);
    int bl = i / DD;
    int l  = bl & (LL-1);
    h[i] = tok[(size_t)x[bl]*DD + d] + pos[l*DD + d];
}

// ---------------- layernorm (writes bf16 hi/lo split directly) ---------------
__global__ __launch_bounds__(256) void layernorm_kernel(
    const float* __restrict__ x, const float* __restrict__ g,
    const float* __restrict__ b, bf16* __restrict__ yh, bf16* __restrict__ yl)
{
    __shared__ float red[16];
    __shared__ float stats[2];
    int row = blockIdx.x;
    int tid = threadIdx.x;
    const float2* xr = (const float2*)(x + (size_t)row*DD);
    float2 v = xr[tid];
    float s = v.x + v.y;
    float q = v.x*v.x + v.y*v.y;
    #pragma unroll
    for (int o = 16; o; o >>= 1) {
        s += __shfl_down_sync(0xffffffffu, s, o);
        q += __shfl_down_sync(0xffffffffu, q, o);
    }
    int w = tid >> 5;
    if ((tid & 31) == 0) { red[w] = s; red[w+8] = q; }
    __syncthreads();
    if (tid < 32) {
        s = (tid < 8) ? red[tid]   : 0.f;
        q = (tid < 8) ? red[tid+8] : 0.f;
        #pragma unroll
        for (int o = 4; o; o >>= 1) {
            s += __shfl_down_sync(0xffffffffu, s, o);
            q += __shfl_down_sync(0xffffffffu, q, o);
        }
        if (tid == 0) {
            float mu  = s * (1.0f/DD);
            float var = q * (1.0f/DD) - mu*mu;
            stats[0] = mu;
            stats[1] = rsqrtf(var + 1e-5f);
        }
    }
    __syncthreads();
    float mu = stats[0], inv = stats[1];
    float2 gg = ((const float2*)g)[tid];
    float2 bb = ((const float2*)b)[tid];
    float ox = (v.x - mu)*inv*gg.x + bb.x;
    float oy = (v.y - mu)*inv*gg.y + bb.y;
    uint32_t hh, ll;
    split2(ox, oy, hh, ll);
    *(uint32_t*)(yh + (size_t)row*DD + 2*tid) = hh;
    *(uint32_t*)(yl + (size_t)row*DD + 2*tid) = ll;
}

// ---------------- weight transpose+split: in [K,N] -> out [N,K] hi/lo --------
__global__ __launch_bounds__(256) void tsplit_kernel(
    const float* __restrict__ in, bf16* __restrict__ hi, bf16* __restrict__ lo,
    int K, int N)
{
    __shared__ float t[32][33];
    int n0 = blockIdx.x * 32, k0 = blockIdx.y * 32;
    int tx = threadIdx.x, ty = threadIdx.y;
    #pragma unroll
    for (int i = ty; i < 32; i += 8)
        t[i][tx] = in[(size_t)(k0+i)*N + n0 + tx];
    __syncthreads();
    #pragma unroll
    for (int i = ty; i < 32; i += 8) {
        float v = t[tx][i];
        bf16 h = __float2bfloat16(v);
        bf16 l = __float2bfloat16(v - __bfloat162float(h));
        size_t o = (size_t)(n0+i)*K + k0 + tx;
        hi[o] = h; lo[o] = l;
    }
}

// ---------------- mma.sync bf16x3 GEMM 128x128, K-chunks of 64 ---------------
// fuse: 0=+bias->f32 C, 1=gelu(+bias)->bf16 hi/lo (Ch,Cl), 2=+bias+res->f32 C,
//       3=plain->f32 C
#define TSTR 72   // smem row stride in bf16 elems (144B: conflict-free ldmatrix)

__global__ __launch_bounds__(256) void tcgemm(
    const bf16* __restrict__ Ah, const bf16* __restrict__ Al,
    const bf16* __restrict__ Bh, const bf16* __restrict__ Bl,
    const float* __restrict__ bias, const float* __restrict__ res,
    float* __restrict__ C, bf16* __restrict__ Ch, bf16* __restrict__ Cl,
    int Kd, int Nd, int fuse)
{
    __shared__ __align__(16) bf16 As[128*TSTR];
    __shared__ __align__(16) bf16 Bs[128*TSTR];
    uint32_t asb = smem_u32(As), bsb = smem_u32(Bs);

    int tid = threadIdx.x, lane = tid & 31, wid = tid >> 5;
    int m0w = (wid >> 2) * 64;
    int n0w = (wid & 3) * 32;
    int bn0  = blockIdx.x * 128;
    int row0 = blockIdx.y * 128;

    float acc[16][4];
    #pragma unroll
    for (int i = 0; i < 16; i++)
        #pragma unroll
        for (int j = 0; j < 4; j++) acc[i][j] = 0.f;

    int kseg  = Kd >> 6;
    int total = 3 * kseg;

    int lr[4], lc[4];
    #pragma unroll
    for (int p = 0; p < 4; p++) {
        int id = tid + (p << 8);
        lr[p] = id >> 3;
        lc[p] = (id & 7) << 3;
    }

    float4 pa[4], pb[4];
    #pragma unroll
    for (int p = 0; p < 4; p++) {
        pa[p] = *(const float4*)(Ah + (size_t)(row0 + lr[p])*Kd + lc[p]);
        pb[p] = *(const float4*)(Bh + (size_t)(bn0 + lr[p])*Kd + lc[p]);
    }

    for (int c = 0; c < total; c++) {
        #pragma unroll
        for (int p = 0; p < 4; p++) {
            *(float4*)(As + lr[p]*TSTR + lc[p]) = pa[p];
            *(float4*)(Bs + lr[p]*TSTR + lc[p]) = pb[p];
        }
        __syncthreads();

        if (c + 1 < total) {
            int cn  = c + 1;
            int seg = cn / kseg;
            int kk  = (cn - seg * kseg) << 6;
            const bf16* Asrc = (seg == 1) ? Al : Ah;
            const bf16* Bsrc = (seg == 2) ? Bl : Bh;
            #pragma unroll
            for (int p = 0; p < 4; p++) {
                pa[p] = *(const float4*)(Asrc + (size_t)(row0 + lr[p])*Kd + kk + lc[p]);
                pb[p] = *(const float4*)(Bsrc + (size_t)(bn0 + lr[p])*Kd + kk + lc[p]);
            }
        }

        #pragma unroll
        for (int ks = 0; ks < 4; ks++) {
            uint32_t af[4][4], bfr[4][2];
            #pragma unroll
            for (int mt = 0; mt < 4; mt++) {
                uint32_t addr = asb +
                    (((m0w + mt*16 + (lane & 15)) * TSTR) +
                     ks*16 + ((lane >> 4) << 3)) * 2;
                LDSM_X4(af[mt][0], af[mt][1], af[mt][2], af[mt][3], addr);
            }
            #pragma unroll
            for (int nt = 0; nt < 4; nt++) {
                uint32_t addr = bsb +
                    (((n0w + nt*8 + (lane & 7)) * TSTR) +
                     ks*16 + (((lane >> 3) & 1) << 3)) * 2;
                LDSM_X2(bfr[nt][0], bfr[nt][1], addr);
            }
            #pragma unroll
            for (int mt = 0; mt < 4; mt++)
                #pragma unroll
                for (int nt = 0; nt < 4; nt++)
                    MMA16816(acc[mt*4 + nt], af[mt], bfr[nt]);
        }
        __syncthreads();
    }

    #pragma unroll
    for (int mt = 0; mt < 4; mt++) {
        int r0 = row0 + m0w + mt*16 + (lane >> 2);
        #pragma unroll
        for (int nt = 0; nt < 4; nt++) {
            int col = bn0 + n0w + nt*8 + ((lane & 3) << 1);
            float2 v0 = make_float2(acc[mt*4+nt][0], acc[mt*4+nt][1]);
            float2 v1 = make_float2(acc[mt*4+nt][2], acc[mt*4+nt][3]);
            if (fuse != 3) {
                float2 bv = *(const float2*)(bias + col);
                v0.x += bv.x; v0.y += bv.y;
                v1.x += bv.x; v1.y += bv.y;
            }
            if (fuse == 1) {
                v0.x = 0.5f*v0.x*(1.0f + erff(v0.x*0.7071067811865475f));
                v0.y = 0.5f*v0.y*(1.0f + erff(v0.y*0.7071067811865475f));
                v1.x = 0.5f*v1.x*(1.0f + erff(v1.x*0.7071067811865475f));
                v1.y = 0.5f*v1.y*(1.0f + erff(v1.y*0.7071067811865475f));
                uint32_t h0, l0, h1, l1;
                split2(v0.x, v0.y, h0, l0);
                split2(v1.x, v1.y, h1, l1);
                *(uint32_t*)(Ch + (size_t)r0*Nd + col)     = h0;
                *(uint32_t*)(Cl + (size_t)r0*Nd + col)     = l0;
                *(uint32_t*)(Ch + (size_t)(r0+8)*Nd + col) = h1;
                *(uint32_t*)(Cl + (size_t)(r0+8)*Nd + col) = l1;
                continue;
            }
            if (fuse == 2) {
                float2 r0v = *(const float2*)(res + (size_t)r0*Nd + col);
                float2 r1v = *(const float2*)(res + (size_t)(r0+8)*Nd + col);
                v0.x += r0v.x; v0.y += r0v.y;
                v1.x += r1v.x; v1.y += r1v.y;
            }
            *(float2*)(C + (size_t)r0*Nd + col)          = v0;
            *(float2*)(C + (size_t)(r0+8)*Nd + col)      = v1;
        }
    }
}

// ---------------- tensor-core flash attention (bf16x3 compensated) -----------
// block: 128 queries x one (b,h); 8 warps, each owns 16 q rows.
// K tiles of 64 keys; softmax fully in registers; writes bf16 hi/lo output.
#define ATQ 128
#define ATK 64
// smem elem offsets (bf16, stride TSTR=72)
#define SQH 0
#define SQL 9216
#define SKH 18432
#define SKL 23040
#define SVH 27648
#define SVL 32256
#define ATTN_SMEM (36864*2)

__global__ __launch_bounds__(256, 2) void attn_kernel(
    const float* __restrict__ qkv,
    bf16* __restrict__ oh, bf16* __restrict__ ol)
{
    extern __shared__ bf16 sm[];
    uint32_t smb = smem_u32(sm);

    int q0 = blockIdx.x * ATQ;
    int hh = blockIdx.y;
    int bb = blockIdx.z;
    const float* base = qkv + (size_t)bb * LL * (3*DD);
    int qoff = hh*HDD;
    int koff = DD + hh*HDD;
    int voff = 2*DD + hh*HDD;

    int tid = threadIdx.x, lane = tid & 31, wid = tid >> 5;
    int wrow0 = q0 + wid*16;

    // load Q tile (128x64 fp32 -> bf16 hi/lo, stride 72)
    #pragma unroll
    for (int p = 0; p < 8; p++) {
        int id = tid + (p << 8);
        int r  = id >> 4;
        int c4 = (id & 15) << 2;
        float4 v = *(const float4*)(base + (size_t)(q0 + r)*(3*DD) + qoff + c4);
        uint32_t h0,l0,h1,l1;
        split2(v.x, v.y, h0, l0);
        split2(v.z, v.w, h1, l1);
        *(uint2*)(sm + SQH + r*TSTR + c4) = make_uint2(h0, h1);
        *(uint2*)(sm + SQL + r*TSTR + c4) = make_uint2(l0, l1);
    }

    float Oa[8][4];
    #pragma unroll
    for (int i = 0; i < 8; i++)
        #pragma unroll
        for (int j = 0; j < 4; j++) Oa[i][j] = 0.f;
    float m0 = -1e30f, m1 = -1e30f, l0s = 0.f, l1s = 0.f;

    // per-thread fragment address components
    int qfb = ((wid*16 + (lane & 15))*TSTR + ((lane >> 4) << 3)) * 2;
    int krow = ((lane >> 4) << 3) + (lane & 7);
    int kcol = (((lane >> 3) & 1) << 3);
    int vrow = (((lane >> 3) & 1) << 3) + (lane & 7);
    int vcol = ((lane >> 4) << 3);
    int mr   = lane >> 2;          // row within 8 (c0/c1); +8 for c2/c3
    int mc2  = (lane & 3) << 1;

    int ntiles = (q0 + ATQ) / ATK;
    for (int t = 0; t < ntiles; t++) {
        int k0 = t * ATK;
        __syncthreads();
        // load K/V tile (64x64 each), split hi/lo
        #pragma unroll
        for (int p = 0; p < 4; p++) {
            int id = tid + (p << 8);
            int r  = id >> 4;
            int c4 = (id & 15) << 2;
            const float* rowp = base + (size_t)(k0 + r)*(3*DD);
            float4 kv = *(const float4*)(rowp + koff + c4);
            float4 vv = *(const float4*)(rowp + voff + c4);
            uint32_t h0,l0,h1,l1;
            split2(kv.x, kv.y, h0, l0); split2(kv.z, kv.w, h1, l1);
            *(uint2*)(sm + SKH + r*TSTR + c4) = make_uint2(h0, h1);
            *(uint2*)(sm + SKL + r*TSTR + c4) = make_uint2(l0, l1);
            split2(vv.x, vv.y, h0, l0); split2(vv.z, vv.w, h1, l1);
            *(uint2*)(sm + SVH + r*TSTR + c4) = make_uint2(h0, h1);
            *(uint2*)(sm + SVL + r*TSTR + c4) = make_uint2(l0, l1);
        }
        __syncthreads();

        if (k0 > wrow0 + 15) continue;   // fully masked for this warp

        // ---- S = scale * Q K^T (compensated) ----
        float Sa[8][4];
        #pragma unroll
        for (int i = 0; i < 8; i++)
            #pragma unroll
            for (int j = 0; j < 4; j++) Sa[i][j] = 0.f;

        #pragma unroll
        for (int ks = 0; ks < 4; ks++) {
            uint32_t qh[4], ql[4];
            LDSM_X4(qh[0],qh[1],qh[2],qh[3], smb + SQH*2 + qfb + ks*32);
            LDSM_X4(ql[0],ql[1],ql[2],ql[3], smb + SQL*2 + qfb + ks*32);
            #pragma unroll
            for (int np = 0; np < 4; np++) {
                uint32_t kf[4];
                uint32_t ka = smb + ((SKH + (np*16 + krow)*TSTR + kcol) * 2) + ks*32;
                LDSM_X4(kf[0],kf[1],kf[2],kf[3], ka);
                uint32_t b01[2] = {kf[0],kf[1]}, b23[2] = {kf[2],kf[3]};
                MMA16816(Sa[2*np],   qh, b01);
                MMA16816(Sa[2*np+1], qh, b23);
                MMA16816(Sa[2*np],   ql, b01);
                MMA16816(Sa[2*np+1], ql, b23);
                uint32_t la = smb + ((SKL + (np*16 + krow)*TSTR + kcol) * 2) + ks*32;
                LDSM_X4(kf[0],kf[1],kf[2],kf[3], la);
                uint32_t c01[2] = {kf[0],kf[1]}, c23[2] = {kf[2],kf[3]};
                MMA16816(Sa[2*np],   qh, c01);
                MMA16816(Sa[2*np+1], qh, c23);
            }
        }

        // scale + causal mask
        #pragma unroll
        for (int nt = 0; nt < 8; nt++)
            #pragma unroll
            for (int j = 0; j < 4; j++) Sa[nt][j] *= 0.125f;
        if (k0 + 63 > wrow0) {
            int r0g = wrow0 + mr, r1g = r0g + 8;
            #pragma unroll
            for (int nt = 0; nt < 8; nt++) {
                int col = k0 + nt*8 + mc2;
                if (col   > r0g) Sa[nt][0] = -1e30f;
                if (col+1 > r0g) Sa[nt][1] = -1e30f;
                if (col   > r1g) Sa[nt][2] = -1e30f;
                if (col+1 > r1g) Sa[nt][3] = -1e30f;
            }
        }

        // ---- online softmax in registers ----
        float rx0 = -1e30f, rx1 = -1e30f;
        #pragma unroll
        for (int nt = 0; nt < 8; nt++) {
            rx0 = fmaxf(rx0, fmaxf(Sa[nt][0], Sa[nt][1]));
            rx1 = fmaxf(rx1, fmaxf(Sa[nt][2], Sa[nt][3]));
        }
        rx0 = fmaxf(rx0, __shfl_xor_sync(0xffffffffu, rx0, 1));
        rx0 = fmaxf(rx0, __shfl_xor_sync(0xffffffffu, rx0, 2));
        rx1 = fmaxf(rx1, __shfl_xor_sync(0xffffffffu, rx1, 1));
        rx1 = fmaxf(rx1, __shfl_xor_sync(0xffffffffu, rx1, 2));
        float mn0 = fmaxf(m0, rx0), mn1 = fmaxf(m1, rx1);
        float a0 = __expf(m0 - mn0), a1 = __expf(m1 - mn1);
        float s0 = 0.f, s1 = 0.f;
        #pragma unroll
        for (int nt = 0; nt < 8; nt++) {
            Sa[nt][0] = __expf(Sa[nt][0] - mn0);
            Sa[nt][1] = __expf(Sa[nt][1] - mn0);
            Sa[nt][2] = __expf(Sa[nt][2] - mn1);
            Sa[nt][3] = __expf(Sa[nt][3] - mn1);
            s0 += Sa[nt][0] + Sa[nt][1];
            s1 += Sa[nt][2] + Sa[nt][3];
        }
        s0 += __shfl_xor_sync(0xffffffffu, s0, 1);
        s0 += __shfl_xor_sync(0xffffffffu, s0, 2);
        s1 += __shfl_xor_sync(0xffffffffu, s1, 1);
        s1 += __shfl_xor_sync(0xffffffffu, s1, 2);
        l0s = l0s*a0 + s0;  l1s = l1s*a1 + s1;
        m0 = mn0; m1 = mn1;
        #pragma unroll
        for (int nt = 0; nt < 8; nt++) {
            Oa[nt][0] *= a0; Oa[nt][1] *= a0;
            Oa[nt][2] *= a1; Oa[nt][3] *= a1;
        }

        // ---- O += P V (compensated); P frags direct from registers ----
        #pragma unroll
        for (int ks = 0; ks < 4; ks++) {
            uint32_t ph[4], pl[4];
            split2(Sa[2*ks][0],   Sa[2*ks][1],   ph[0], pl[0]);
            split2(Sa[2*ks][2],   Sa[2*ks][3],   ph[1], pl[1]);
            split2(Sa[2*ks+1][0], Sa[2*ks+1][1], ph[2], pl[2]);
            split2(Sa[2*ks+1][2], Sa[2*ks+1][3], ph[3], pl[3]);
            #pragma unroll
            for (int np = 0; np < 4; np++) {
                uint32_t vf[4];
                uint32_t va = smb + ((SVH + (ks*16 + vrow)*TSTR + np*16 + vcol) * 2);
                LDSM_X4_T(vf[0],vf[1],vf[2],vf[3], va);
                uint32_t b01[2] = {vf[0],vf[1]}, b23[2] = {vf[2],vf[3]};
                MMA16816(Oa[2*np],   ph, b01);
                MMA16816(Oa[2*np+1], ph, b23);
                MMA16816(Oa[2*np],   pl, b01);
                MMA16816(Oa[2*np+1], pl, b23);
                uint32_t la = smb + ((SVL + (ks*16 + vrow)*TSTR + np*16 + vcol) * 2);
                LDSM_X4_T(vf[0],vf[1],vf[2],vf[3], la);
                uint32_t c01[2] = {vf[0],vf[1]}, c23[2] = {vf[2],vf[3]};
                MMA16816(Oa[2*np],   ph, c01);
                MMA16816(Oa[2*np+1], ph, c23);
            }
        }
    }

    // ---- write output as bf16 hi/lo ----
    float inv0 = 1.0f / l0s, inv1 = 1.0f / l1s;
    size_t r0g = (size_t)bb*LL + wrow0 + mr;
    size_t r1g = r0g + 8;
    int cb = hh*HDD + mc2;
    #pragma unroll
    for (int nt = 0; nt < 8; nt++) {
        uint32_t h0, l0, h1, l1;
        split2(Oa[nt][0]*inv0, Oa[nt][1]*inv0, h0, l0);
        split2(Oa[nt][2]*inv1, Oa[nt][3]*inv1, h1, l1);
        int col = cb + nt*8;
        *(uint32_t*)(oh + r0g*DD + col) = h0;
        *(uint32_t*)(ol + r0g*DD + col) = l0;
        *(uint32_t*)(oh + r1g*DD + col) = h1;
        *(uint32_t*)(ol + r1g*DD + col) = l1;
    }
}

// ---------------- launcher ----------------------------------------------------
extern "C" void kernel_launch(void* const* d_in, const int* in_sizes, int n_in,
                              void* d_out, int out_size)
{
    const int*   x     = (const int*)  d_in[0];
    const float* tok   = (const float*)d_in[1];
    const float* pos   = (const float*)d_in[2];
    const float* ln1g  = (const float*)d_in[3];
    const float* ln1b  = (const float*)d_in[4];
    const float* qkvw  = (const float*)d_in[5];
    const float* qkvb  = (const float*)d_in[6];
    const float* outw  = (const float*)d_in[7];
    const float* outb  = (const float*)d_in[8];
    const float* ln2g  = (const float*)d_in[9];
    const float* ln2b  = (const float*)d_in[10];
    const float* w1    = (const float*)d_in[11];
    const float* b1    = (const float*)d_in[12];
    const float* w2    = (const float*)d_in[13];
    const float* b2    = (const float*)d_in[14];
    const float* lnfg  = (const float*)d_in[15];
    const float* lnfb  = (const float*)d_in[16];
    const float* headw = (const float*)d_in[17];
    float* out = (float*)d_out;

    float *h, *big;
    bf16 *xh, *xl, *mh, *ml, *wh, *wl;
    cudaGetSymbolAddress((void**)&h,   g_h);
    cudaGetSymbolAddress((void**)&big, g_big);
    cudaGetSymbolAddress((void**)&xh,  g_xh);
    cudaGetSymbolAddress((void**)&xl,  g_xl);
    cudaGetSymbolAddress((void**)&mh,  g_mh);
    cudaGetSymbolAddress((void**)&ml,  g_ml);
    cudaGetSymbolAddress((void**)&wh,  g_wh);
    cudaGetSymbolAddress((void**)&wl,  g_wl);

    cudaFuncSetAttribute(attn_kernel,
        cudaFuncAttributeMaxDynamicSharedMemorySize, ATTN_SMEM);

    // weight prep: transpose [K,N] -> [N,K] + bf16 hi/lo split
    dim3 tb(32, 8);
    for (int i = 0; i < NLL; i++) {
        tsplit_kernel<<<dim3(1536/32, 512/32), tb>>>(
            qkvw + (size_t)i*DD*3*DD, wh + W_QKV0 + (size_t)i*786432,
            wl + W_QKV0 + (size_t)i*786432, 512, 1536);
        tsplit_kernel<<<dim3(512/32, 512/32), tb>>>(
            outw + (size_t)i*DD*DD, wh + W_OUT0 + (size_t)i*262144,
            wl + W_OUT0 + (size_t)i*262144, 512, 512);
        tsplit_kernel<<<dim3(2048/32, 512/32), tb>>>(
            w1 + (size_t)i*DD*DMM, wh + W_W10 + (size_t)i*1048576,
            wl + W_W10 + (size_t)i*1048576, 512, 2048);
        tsplit_kernel<<<dim3(512/32, 2048/32), tb>>>(
            w2 + (size_t)i*DMM*DD, wh + W_W20 + (size_t)i*1048576,
            wl + W_W20 + (size_t)i*1048576, 2048, 512);
    }
    tsplit_kernel<<<dim3(32000/32, 512/32), tb>>>(
        headw, wh + W_HEAD, wl + W_HEAD, 512, 32000);

    embed_kernel<<<(MM*DD)/256, 256>>>(x, tok, pos, h);

    for (int i = 0; i < NLL; i++) {
        // attn block
        layernorm_kernel<<<MM, 256>>>(h, ln1g + i*DD, ln1b + i*DD, xh, xl);
        tcgemm<<<dim3(1536/128, MM/128), 256>>>(
            xh, xl, wh + W_QKV0 + (size_t)i*786432, wl + W_QKV0 + (size_t)i*786432,
            qkvb + (size_t)i*3*DD, nullptr, big, nullptr, nullptr, 512, 1536, 0);
        attn_kernel<<<dim3(LL/ATQ, NHH, BB), 256, ATTN_SMEM>>>(big, xh, xl);
        tcgemm<<<dim3(512/128, MM/128), 256>>>(
            xh, xl, wh + W_OUT0 + (size_t)i*262144, wl + W_OUT0 + (size_t)i*262144,
            outb + (size_t)i*DD, h, h, nullptr, nullptr, 512, 512, 2);
        // mlp block
        layernorm_kernel<<<MM, 256>>>(h, ln2g + i*DD, ln2b + i*DD, xh, xl);
        tcgemm<<<dim3(2048/128, MM/128), 256>>>(
            xh, xl, wh + W_W10 + (size_t)i*1048576, wl + W_W10 + (size_t)i*1048576,
            b1 + (size_t)i*DMM, nullptr, nullptr, mh, ml, 512, 2048, 1);
        tcgemm<<<dim3(512/128, MM/128), 256>>>(
            mh, ml, wh + W_W20 + (size_t)i*1048576, wl + W_W20 + (size_t)i*1048576,
            b2 + (size_t)i*DD, h, h, nullptr, nullptr, 2048, 512, 2);
    }

    layernorm_kernel<<<MM, 256>>>(h, lnfg, lnfb, xh, xl);
    tcgemm<<<dim3(VV/128, MM/128), 256>>>(
        xh, xl, wh + W_HEAD, wl + W_HEAD,
        nullptr, nullptr, out, nullptr, nullptr, 512, VV, 3);
}

// round 11
// speedup vs baseline: 2.8752x; 1.1178x over previous
#include <cuda_runtime.h>
#include <cuda_bf16.h>
#include <math.h>
#include <stdint.h>

typedef __nv_bfloat16 bf16;

// Problem dims
#define BB 2
#define LL 2048
#define DD 512
#define NHH 8
#define NLL 4
#define DMM 2048
#define VV 32000
#define HDD 64
#define MM (BB*LL)          // 4096 rows

// ---------------- PTX helpers ------------------------------------------------
__device__ __forceinline__ uint32_t smem_u32(const void* p) {
    uint32_t a;
    asm("{ .reg .u64 t; cvta.to.shared.u64 t, %1; cvt.u32.u64 %0, t; }"
        : "=r"(a) : "l"(p));
    return a;
}

#define LDSM_X4(r0,r1,r2,r3,addr) \
    asm volatile("ldmatrix.sync.aligned.m8n8.x4.shared.b16 {%0,%1,%2,%3}, [%4];" \
        : "=r"(r0), "=r"(r1), "=r"(r2), "=r"(r3) : "r"(addr))
#define LDSM_X4_T(r0,r1,r2,r3,addr) \
    asm volatile("ldmatrix.sync.aligned.m8n8.x4.trans.shared.b16 {%0,%1,%2,%3}, [%4];" \
        : "=r"(r0), "=r"(r1), "=r"(r2), "=r"(r3) : "r"(addr))
#define MMA16816(d, a, b) \
    asm volatile("mma.sync.aligned.m16n8k16.row.col.f32.bf16.bf16.f32 " \
        "{%0,%1,%2,%3}, {%4,%5,%6,%7}, {%8,%9}, {%0,%1,%2,%3};" \
        : "+f"((d)[0]), "+f"((d)[1]), "+f"((d)[2]), "+f"((d)[3]) \
        : "r"((a)[0]), "r"((a)[1]), "r"((a)[2]), "r"((a)[3]), \
          "r"((b)[0]), "r"((b)[1]))
#define CP16(dst, src) \
    asm volatile("cp.async.cg.shared.global [%0], [%1], 16;" :: "r"(dst), "l"(src))
#define CP_COMMIT() asm volatile("cp.async.commit_group;" ::: "memory")
#define CP_WAIT1()  asm volatile("cp.async.wait_group 1;" ::: "memory")
#define CP_WAIT0()  asm volatile("cp.async.wait_group 0;" ::: "memory")

// pack two fp32 into bf16x2 hi + residual-lo words
__device__ __forceinline__ void split2(float a, float b, uint32_t &h, uint32_t &l) {
    bf16 ha = __float2bfloat16(a), hb = __float2bfloat16(b);
    float ra = a - __bfloat162float(ha);
    float rb = b - __bfloat162float(hb);
    h = (uint32_t)__bfloat16_as_ushort(ha) |
        ((uint32_t)__bfloat16_as_ushort(hb) << 16);
    l = (uint32_t)__bfloat16_as_ushort(__float2bfloat16(ra)) |
        ((uint32_t)__bfloat16_as_ushort(__float2bfloat16(rb)) << 16);
}

// ---------------- scratch (device globals) -----------------------------------
__device__ float g_h  [MM*DD];        // residual stream
__device__ float g_big[MM*3*DD];      // qkv fp32
__device__ bf16  g_xh [MM*DD];        // activation hi (LN out / attn out)
__device__ bf16  g_xl [MM*DD];
__device__ bf16  g_mh [MM*DMM];       // mlp hidden hi/lo
__device__ bf16  g_ml [MM*DMM];

// transposed+split weights [N,K] bf16
#define W_QKV0 0
#define W_OUT0 3145728
#define W_W10  4194304
#define W_W20  8388608
#define W_HEAD 12582912
#define WTOT   28966912
__device__ bf16 g_wh[WTOT];
__device__ bf16 g_wl[WTOT];

// ---------------- embedding --------------------------------------------------
__global__ void embed_kernel(const int* __restrict__ x,
                             const float* __restrict__ tok,
                             const float* __restrict__ pos,
                             float* __restrict__ h)
{
    int i = blockIdx.x * blockDim.x + threadIdx.x;
    int d  = i & (DD-1);
    int bl = i / DD;
    int l  = bl & (LL-1);
    h[i] = tok[(size_t)x[bl]*DD + d] + pos[l*DD + d];
}

// ---------------- layernorm (writes bf16 hi/lo split directly) ---------------
__global__ __launch_bounds__(256) void layernorm_kernel(
    const float* __restrict__ x, const float* __restrict__ g,
    const float* __restrict__ b, bf16* __restrict__ yh, bf16* __restrict__ yl)
{
    __shared__ float red[16];
    __shared__ float stats[2];
    int row = blockIdx.x;
    int tid = threadIdx.x;
    const float2* xr = (const float2*)(x + (size_t)row*DD);
    float2 v = xr[tid];
    float s = v.x + v.y;
    float q = v.x*v.x + v.y*v.y;
    #pragma unroll
    for (int o = 16; o; o >>= 1) {
        s += __shfl_down_sync(0xffffffffu, s, o);
        q += __shfl_down_sync(0xffffffffu, q, o);
    }
    int w = tid >> 5;
    if ((tid & 31) == 0) { red[w] = s; red[w+8] = q; }
    __syncthreads();
    if (tid < 32) {
        s = (tid < 8) ? red[tid]   : 0.f;
        q = (tid < 8) ? red[tid+8] : 0.f;
        #pragma unroll
        for (int o = 4; o; o >>= 1) {
            s += __shfl_down_sync(0xffffffffu, s, o);
            q += __shfl_down_sync(0xffffffffu, q, o);
        }
        if (tid == 0) {
            float mu  = s * (1.0f/DD);
            float var = q * (1.0f/DD) - mu*mu;
            stats[0] = mu;
            stats[1] = rsqrtf(var + 1e-5f);
        }
    }
    __syncthreads();
    float mu = stats[0], inv = stats[1];
    float2 gg = ((const float2*)g)[tid];
    float2 bb = ((const float2*)b)[tid];
    float ox = (v.x - mu)*inv*gg.x + bb.x;
    float oy = (v.y - mu)*inv*gg.y + bb.y;
    uint32_t hh, ll;
    split2(ox, oy, hh, ll);
    *(uint32_t*)(yh + (size_t)row*DD + 2*tid) = hh;
    *(uint32_t*)(yl + (size_t)row*DD + 2*tid) = ll;
}

// ---------------- weight transpose+split: in [K,N] -> out [N,K] hi/lo --------
__global__ __launch_bounds__(256) void tsplit_kernel(
    const float* __restrict__ in, bf16* __restrict__ hi, bf16* __restrict__ lo,
    int K, int N)
{
    __shared__ float t[32][33];
    int n0 = blockIdx.x * 32, k0 = blockIdx.y * 32;
    int tx = threadIdx.x, ty = threadIdx.y;
    #pragma unroll
    for (int i = ty; i < 32; i += 8)
        t[i][tx] = in[(size_t)(k0+i)*N + n0 + tx];
    __syncthreads();
    #pragma unroll
    for (int i = ty; i < 32; i += 8) {
        float v = t[tx][i];
        bf16 h = __float2bfloat16(v);
        bf16 l = __float2bfloat16(v - __bfloat162float(h));
        size_t o = (size_t)(n0+i)*K + k0 + tx;
        hi[o] = h; lo[o] = l;
    }
}

// ---------------- fused-pass bf16x3 GEMM, cp.async 2-stage -------------------
// CTA tile 128 x BN, warp tile 64x64, BN threads.
// Per k64 chunk loads Ah,Al,Bh,Bl once; computes AhBh + AlBh + AhBl.
// fuse: 0=+bias->f32 C, 1=gelu(+bias)->bf16 hi/lo, 2=+bias+res->f32, 3=plain
#define TSTR 72   // smem row stride in bf16 elems (144B: conflict-free ldmatrix)

template<int BN>
__global__ __launch_bounds__(BN) void tcgemm(
    const bf16* __restrict__ Ahp, const bf16* __restrict__ Alp,
    const bf16* __restrict__ Bhp, const bf16* __restrict__ Blp,
    const float* __restrict__ bias, const float* __restrict__ res,
    float* __restrict__ C, bf16* __restrict__ Ch, bf16* __restrict__ Cl,
    int Kd, int Nd, int fuse)
{
    constexpr int NGRP = BN/64;
    constexpr int NT = BN;
    constexpr int AE = 128*TSTR;            // elems per A tile
    constexpr int BE = BN*TSTR;
    constexpr int STAGE_B = (2*AE + 2*BE)*2;

    extern __shared__ bf16 sm[];
    uint32_t smb = smem_u32(sm);

    int tid = threadIdx.x, lane = tid & 31, wid = tid >> 5;
    int m0w = (wid / NGRP) * 64;
    int n0w = (wid % NGRP) * 64;
    int bn0  = blockIdx.x * BN;
    int row0 = blockIdx.y * 128;

    float acc[4][8][4];
    #pragma unroll
    for (int i = 0; i < 4; i++)
        #pragma unroll
        for (int j = 0; j < 8; j++)
            #pragma unroll
            for (int k = 0; k < 4; k++) acc[i][j][k] = 0.f;

    int kseg = Kd >> 6;

    auto load_stage = [&](int buf, int kk) {
        uint32_t sb = smb + buf*STAGE_B;
        #pragma unroll
        for (int p = 0; p < 1024/NT; p++) {
            int id = tid + p*NT; int r = id>>3, cc = (id&7)<<3;
            CP16(sb + (r*TSTR + cc)*2,
                 Ahp + (size_t)(row0+r)*Kd + kk + cc);
        }
        #pragma unroll
        for (int p = 0; p < 1024/NT; p++) {
            int id = tid + p*NT; int r = id>>3, cc = (id&7)<<3;
            CP16(sb + (AE + r*TSTR + cc)*2,
                 Alp + (size_t)(row0+r)*Kd + kk + cc);
        }
        #pragma unroll
        for (int p = 0; p < 8; p++) {
            int id = tid + p*NT; int r = id>>3, cc = (id&7)<<3;
            CP16(sb + (2*AE + r*TSTR + cc)*2,
                 Bhp + (size_t)(bn0+r)*Kd + kk + cc);
        }
        #pragma unroll
        for (int p = 0; p < 8; p++) {
            int id = tid + p*NT; int r = id>>3, cc = (id&7)<<3;
            CP16(sb + (2*AE + BE + r*TSTR + cc)*2,
                 Blp + (size_t)(bn0+r)*Kd + kk + cc);
        }
    };

    load_stage(0, 0);
    CP_COMMIT();

    for (int c = 0; c < kseg; c++) {
        if (c + 1 < kseg) {
            load_stage((c+1)&1, (c+1)<<6);
            CP_COMMIT();
            CP_WAIT1();
        } else {
            CP_WAIT0();
        }
        __syncthreads();

        uint32_t ab  = smb + (c&1)*STAGE_B;
        uint32_t alb = ab + AE*2;
        uint32_t bhb = ab + 2*AE*2;
        uint32_t blb = bhb + BE*2;

        #pragma unroll
        for (int ks = 0; ks < 4; ks++) {
            uint32_t ah4[4][4], al4[4][4];
            int aoff = ((m0w + (lane & 15))*TSTR + ks*16 + ((lane >> 4) << 3)) * 2;
            #pragma unroll
            for (int mt = 0; mt < 4; mt++) {
                LDSM_X4(ah4[mt][0],ah4[mt][1],ah4[mt][2],ah4[mt][3],
                        ab  + aoff + mt*16*TSTR*2);
                LDSM_X4(al4[mt][0],al4[mt][1],al4[mt][2],al4[mt][3],
                        alb + aoff + mt*16*TSTR*2);
            }
            int boff = ((n0w + ((lane >> 4) << 3) + (lane & 7))*TSTR +
                        ks*16 + (((lane >> 3) & 1) << 3)) * 2;
            #pragma unroll
            for (int nt2 = 0; nt2 < 4; nt2++) {
                uint32_t bh4[4], bl4[4];
                LDSM_X4(bh4[0],bh4[1],bh4[2],bh4[3], bhb + boff + nt2*16*TSTR*2);
                LDSM_X4(bl4[0],bl4[1],bl4[2],bl4[3], blb + boff + nt2*16*TSTR*2);
                uint32_t bh01[2]={bh4[0],bh4[1]}, bh23[2]={bh4[2],bh4[3]};
                uint32_t bl01[2]={bl4[0],bl4[1]}, bl23[2]={bl4[2],bl4[3]};
                #pragma unroll
                for (int mt = 0; mt < 4; mt++) {
                    MMA16816(acc[mt][2*nt2],   ah4[mt], bh01);
                    MMA16816(acc[mt][2*nt2+1], ah4[mt], bh23);
                }
                #pragma unroll
                for (int mt = 0; mt < 4; mt++) {
                    MMA16816(acc[mt][2*nt2],   al4[mt], bh01);
                    MMA16816(acc[mt][2*nt2+1], al4[mt], bh23);
                }
                #pragma unroll
                for (int mt = 0; mt < 4; mt++) {
                    MMA16816(acc[mt][2*nt2],   ah4[mt], bl01);
                    MMA16816(acc[mt][2*nt2+1], ah4[mt], bl23);
                }
            }
        }
        __syncthreads();
    }

    // epilogue
    #pragma unroll
    for (int mt = 0; mt < 4; mt++) {
        int r0 = row0 + m0w + mt*16 + (lane >> 2);
        #pragma unroll
        for (int nt = 0; nt < 8; nt++) {
            int col = bn0 + n0w + nt*8 + ((lane & 3) << 1);
            float2 v0 = make_float2(acc[mt][nt][0], acc[mt][nt][1]);
            float2 v1 = make_float2(acc[mt][nt][2], acc[mt][nt][3]);
            if (fuse != 3) {
                float2 bv = *(const float2*)(bias + col);
                v0.x += bv.x; v0.y += bv.y;
                v1.x += bv.x; v1.y += bv.y;
            }
            if (fuse == 1) {
                v0.x = 0.5f*v0.x*(1.0f + erff(v0.x*0.7071067811865475f));
                v0.y = 0.5f*v0.y*(1.0f + erff(v0.y*0.7071067811865475f));
                v1.x = 0.5f*v1.x*(1.0f + erff(v1.x*0.7071067811865475f));
                v1.y = 0.5f*v1.y*(1.0f + erff(v1.y*0.7071067811865475f));
                uint32_t h0, l0, h1, l1;
                split2(v0.x, v0.y, h0, l0);
                split2(v1.x, v1.y, h1, l1);
                *(uint32_t*)(Ch + (size_t)r0*Nd + col)     = h0;
                *(uint32_t*)(Cl + (size_t)r0*Nd + col)     = l0;
                *(uint32_t*)(Ch + (size_t)(r0+8)*Nd + col) = h1;
                *(uint32_t*)(Cl + (size_t)(r0+8)*Nd + col) = l1;
                continue;
            }
            if (fuse == 2) {
                float2 r0v = *(const float2*)(res + (size_t)r0*Nd + col);
                float2 r1v = *(const float2*)(res + (size_t)(r0+8)*Nd + col);
                v0.x += r0v.x; v0.y += r0v.y;
                v1.x += r1v.x; v1.y += r1v.y;
            }
            *(float2*)(C + (size_t)r0*Nd + col)     = v0;
            *(float2*)(C + (size_t)(r0+8)*Nd + col) = v1;
        }
    }
}

#define GS256 221184
#define GS128 147456

// ---------------- tensor-core flash attention (bf16x3 compensated) -----------
#define ATQ 128
#define ATK 64
#define SQH 0
#define SQL 9216
#define SKH 18432
#define SKL 23040
#define SVH 27648
#define SVL 32256
#define ATTN_SMEM (36864*2)

#define LDSM_X2(r0,r1,addr) \
    asm volatile("ldmatrix.sync.aligned.m8n8.x2.shared.b16 {%0,%1}, [%2];" \
        : "=r"(r0), "=r"(r1) : "r"(addr))

__global__ __launch_bounds__(256, 2) void attn_kernel(
    const float* __restrict__ qkv,
    bf16* __restrict__ oh, bf16* __restrict__ ol)
{
    extern __shared__ bf16 smatt[];
    bf16* sm = smatt;
    uint32_t smb = smem_u32(sm);

    int q0 = blockIdx.x * ATQ;
    int hh = blockIdx.y;
    int bb = blockIdx.z;
    const float* base = qkv + (size_t)bb * LL * (3*DD);
    int qoff = hh*HDD;
    int koff = DD + hh*HDD;
    int voff = 2*DD + hh*HDD;

    int tid = threadIdx.x, lane = tid & 31, wid = tid >> 5;
    int wrow0 = q0 + wid*16;

    #pragma unroll
    for (int p = 0; p < 8; p++) {
        int id = tid + (p << 8);
        int r  = id >> 4;
        int c4 = (id & 15) << 2;
        float4 v = *(const float4*)(base + (size_t)(q0 + r)*(3*DD) + qoff + c4);
        uint32_t h0,l0,h1,l1;
        split2(v.x, v.y, h0, l0);
        split2(v.z, v.w, h1, l1);
        *(uint2*)(sm + SQH + r*TSTR + c4) = make_uint2(h0, h1);
        *(uint2*)(sm + SQL + r*TSTR + c4) = make_uint2(l0, l1);
    }

    float Oa[8][4];
    #pragma unroll
    for (int i = 0; i < 8; i++)
        #pragma unroll
        for (int j = 0; j < 4; j++) Oa[i][j] = 0.f;
    float m0 = -1e30f, m1 = -1e30f, l0s = 0.f, l1s = 0.f;

    int qfb = ((wid*16 + (lane & 15))*TSTR + ((lane >> 4) << 3)) * 2;
    int krow = ((lane >> 4) << 3) + (lane & 7);
    int kcol = (((lane >> 3) & 1) << 3);
    int vrow = (((lane >> 3) & 1) << 3) + (lane & 7);
    int vcol = ((lane >> 4) << 3);
    int mr   = lane >> 2;
    int mc2  = (lane & 3) << 1;

    int ntiles = (q0 + ATQ) / ATK;
    for (int t = 0; t < ntiles; t++) {
        int k0 = t * ATK;
        __syncthreads();
        #pragma unroll
        for (int p = 0; p < 4; p++) {
            int id = tid + (p << 8);
            int r  = id >> 4;
            int c4 = (id & 15) << 2;
            const float* rowp = base + (size_t)(k0 + r)*(3*DD);
            float4 kv = *(const float4*)(rowp + koff + c4);
            float4 vv = *(const float4*)(rowp + voff + c4);
            uint32_t h0,l0,h1,l1;
            split2(kv.x, kv.y, h0, l0); split2(kv.z, kv.w, h1, l1);
            *(uint2*)(sm + SKH + r*TSTR + c4) = make_uint2(h0, h1);
            *(uint2*)(sm + SKL + r*TSTR + c4) = make_uint2(l0, l1);
            split2(vv.x, vv.y, h0, l0); split2(vv.z, vv.w, h1, l1);
            *(uint2*)(sm + SVH + r*TSTR + c4) = make_uint2(h0, h1);
            *(uint2*)(sm + SVL + r*TSTR + c4) = make_uint2(l0, l1);
        }
        __syncthreads();

        if (k0 > wrow0 + 15) continue;

        float Sa[8][4];
        #pragma unroll
        for (int i = 0; i < 8; i++)
            #pragma unroll
            for (int j = 0; j < 4; j++) Sa[i][j] = 0.f;

        #pragma unroll
        for (int ks = 0; ks < 4; ks++) {
            uint32_t qh[4], ql[4];
            LDSM_X4(qh[0],qh[1],qh[2],qh[3], smb + SQH*2 + qfb + ks*32);
            LDSM_X4(ql[0],ql[1],ql[2],ql[3], smb + SQL*2 + qfb + ks*32);
            #pragma unroll
            for (int np = 0; np < 4; np++) {
                uint32_t kf[4];
                uint32_t ka = smb + ((SKH + (np*16 + krow)*TSTR + kcol) * 2) + ks*32;
                LDSM_X4(kf[0],kf[1],kf[2],kf[3], ka);
                uint32_t b01[2] = {kf[0],kf[1]}, b23[2] = {kf[2],kf[3]};
                MMA16816(Sa[2*np],   qh, b01);
                MMA16816(Sa[2*np+1], qh, b23);
                MMA16816(Sa[2*np],   ql, b01);
                MMA16816(Sa[2*np+1], ql, b23);
                uint32_t la = smb + ((SKL + (np*16 + krow)*TSTR + kcol) * 2) + ks*32;
                LDSM_X4(kf[0],kf[1],kf[2],kf[3], la);
                uint32_t c01[2] = {kf[0],kf[1]}, c23[2] = {kf[2],kf[3]};
                MMA16816(Sa[2*np],   qh, c01);
                MMA16816(Sa[2*np+1], qh, c23);
            }
        }

        #pragma unroll
        for (int nt = 0; nt < 8; nt++)
            #pragma unroll
            for (int j = 0; j < 4; j++) Sa[nt][j] *= 0.125f;
        if (k0 + 63 > wrow0) {
            int r0g = wrow0 + mr, r1g = r0g + 8;
            #pragma unroll
            for (int nt = 0; nt < 8; nt++) {
                int col = k0 + nt*8 + mc2;
                if (col   > r0g) Sa[nt][0] = -1e30f;
                if (col+1 > r0g) Sa[nt][1] = -1e30f;
                if (col   > r1g) Sa[nt][2] = -1e30f;
                if (col+1 > r1g) Sa[nt][3] = -1e30f;
            }
        }

        float rx0 = -1e30f, rx1 = -1e30f;
        #pragma unroll
        for (int nt = 0; nt < 8; nt++) {
            rx0 = fmaxf(rx0, fmaxf(Sa[nt][0], Sa[nt][1]));
            rx1 = fmaxf(rx1, fmaxf(Sa[nt][2], Sa[nt][3]));
        }
        rx0 = fmaxf(rx0, __shfl_xor_sync(0xffffffffu, rx0, 1));
        rx0 = fmaxf(rx0, __shfl_xor_sync(0xffffffffu, rx0, 2));
        rx1 = fmaxf(rx1, __shfl_xor_sync(0xffffffffu, rx1, 1));
        rx1 = fmaxf(rx1, __shfl_xor_sync(0xffffffffu, rx1, 2));
        float mn0 = fmaxf(m0, rx0), mn1 = fmaxf(m1, rx1);
        float a0 = __expf(m0 - mn0), a1 = __expf(m1 - mn1);
        float s0 = 0.f, s1 = 0.f;
        #pragma unroll
        for (int nt = 0; nt < 8; nt++) {
            Sa[nt][0] = __expf(Sa[nt][0] - mn0);
            Sa[nt][1] = __expf(Sa[nt][1] - mn0);
            Sa[nt][2] = __expf(Sa[nt][2] - mn1);
            Sa[nt][3] = __expf(Sa[nt][3] - mn1);
            s0 += Sa[nt][0] + Sa[nt][1];
            s1 += Sa[nt][2] + Sa[nt][3];
        }
        s0 += __shfl_xor_sync(0xffffffffu, s0, 1);
        s0 += __shfl_xor_sync(0xffffffffu, s0, 2);
        s1 += __shfl_xor_sync(0xffffffffu, s1, 1);
        s1 += __shfl_xor_sync(0xffffffffu, s1, 2);
        l0s = l0s*a0 + s0;  l1s = l1s*a1 + s1;
        m0 = mn0; m1 = mn1;
        #pragma unroll
        for (int nt = 0; nt < 8; nt++) {
            Oa[nt][0] *= a0; Oa[nt][1] *= a0;
            Oa[nt][2] *= a1; Oa[nt][3] *= a1;
        }

        #pragma unroll
        for (int ks = 0; ks < 4; ks++) {
            uint32_t ph[4], pl[4];
            split2(Sa[2*ks][0],   Sa[2*ks][1],   ph[0], pl[0]);
            split2(Sa[2*ks][2],   Sa[2*ks][3],   ph[1], pl[1]);
            split2(Sa[2*ks+1][0], Sa[2*ks+1][1], ph[2], pl[2]);
            split2(Sa[2*ks+1][2], Sa[2*ks+1][3], ph[3], pl[3]);
            #pragma unroll
            for (int np = 0; np < 4; np++) {
                uint32_t vf[4];
                uint32_t va = smb + ((SVH + (ks*16 + vrow)*TSTR + np*16 + vcol) * 2);
                LDSM_X4_T(vf[0],vf[1],vf[2],vf[3], va);
                uint32_t b01[2] = {vf[0],vf[1]}, b23[2] = {vf[2],vf[3]};
                MMA16816(Oa[2*np],   ph, b01);
                MMA16816(Oa[2*np+1], ph, b23);
                MMA16816(Oa[2*np],   pl, b01);
                MMA16816(Oa[2*np+1], pl, b23);
                uint32_t la = smb + ((SVL + (ks*16 + vrow)*TSTR + np*16 + vcol) * 2);
                LDSM_X4_T(vf[0],vf[1],vf[2],vf[3], la);
                uint32_t c01[2] = {vf[0],vf[1]}, c23[2] = {vf[2],vf[3]};
                MMA16816(Oa[2*np],   ph, c01);
                MMA16816(Oa[2*np+1], ph, c23);
            }
        }
    }

    float inv0 = 1.0f / l0s, inv1 = 1.0f / l1s;
    size_t r0g = (size_t)bb*LL + wrow0 + mr;
    size_t r1g = r0g + 8;
    int cb = hh*HDD + mc2;
    #pragma unroll
    for (int nt = 0; nt < 8; nt++) {
        uint32_t h0, l0, h1, l1;
        split2(Oa[nt][0]*inv0, Oa[nt][1]*inv0, h0, l0);
        split2(Oa[nt][2]*inv1, Oa[nt][3]*inv1, h1, l1);
        int col = cb + nt*8;
        *(uint32_t*)(oh + r0g*DD + col) = h0;
        *(uint32_t*)(ol + r0g*DD + col) = l0;
        *(uint32_t*)(oh + r1g*DD + col) = h1;
        *(uint32_t*)(ol + r1g*DD + col) = l1;
    }
}

// ---------------- launcher ----------------------------------------------------
extern "C" void kernel_launch(void* const* d_in, const int* in_sizes, int n_in,
                              void* d_out, int out_size)
{
    const int*   x     = (const int*)  d_in[0];
    const float* tok   = (const float*)d_in[1];
    const float* pos   = (const float*)d_in[2];
    const float* ln1g  = (const float*)d_in[3];
    const float* ln1b  = (const float*)d_in[4];
    const float* qkvw  = (const float*)d_in[5];
    const float* qkvb  = (const float*)d_in[6];
    const float* outw  = (const float*)d_in[7];
    const float* outb  = (const float*)d_in[8];
    const float* ln2g  = (const float*)d_in[9];
    const float* ln2b  = (const float*)d_in[10];
    const float* w1    = (const float*)d_in[11];
    const float* b1    = (const float*)d_in[12];
    const float* w2    = (const float*)d_in[13];
    const float* b2    = (const float*)d_in[14];
    const float* lnfg  = (const float*)d_in[15];
    const float* lnfb  = (const float*)d_in[16];
    const float* headw = (const float*)d_in[17];
    float* out = (float*)d_out;

    float *h, *big;
    bf16 *xh, *xl, *mh, *ml, *wh, *wl;
    cudaGetSymbolAddress((void**)&h,   g_h);
    cudaGetSymbolAddress((void**)&big, g_big);
    cudaGetSymbolAddress((void**)&xh,  g_xh);
    cudaGetSymbolAddress((void**)&xl,  g_xl);
    cudaGetSymbolAddress((void**)&mh,  g_mh);
    cudaGetSymbolAddress((void**)&ml,  g_ml);
    cudaGetSymbolAddress((void**)&wh,  g_wh);
    cudaGetSymbolAddress((void**)&wl,  g_wl);

    cudaFuncSetAttribute(attn_kernel,
        cudaFuncAttributeMaxDynamicSharedMemorySize, ATTN_SMEM);
    cudaFuncSetAttribute(tcgemm<256>,
        cudaFuncAttributeMaxDynamicSharedMemorySize, GS256);
    cudaFuncSetAttribute(tcgemm<128>,
        cudaFuncAttributeMaxDynamicSharedMemorySize, GS128);

    // weight prep: transpose [K,N] -> [N,K] + bf16 hi/lo split
    dim3 tb(32, 8);
    for (int i = 0; i < NLL; i++) {
        tsplit_kernel<<<dim3(1536/32, 512/32), tb>>>(
            qkvw + (size_t)i*DD*3*DD, wh + W_QKV0 + (size_t)i*786432,
            wl + W_QKV0 + (size_t)i*786432, 512, 1536);
        tsplit_kernel<<<dim3(512/32, 512/32), tb>>>(
            outw + (size_t)i*DD*DD, wh + W_OUT0 + (size_t)i*262144,
            wl + W_OUT0 + (size_t)i*262144, 512, 512);
        tsplit_kernel<<<dim3(2048/32, 512/32), tb>>>(
            w1 + (size_t)i*DD*DMM, wh + W_W10 + (size_t)i*1048576,
            wl + W_W10 + (size_t)i*1048576, 512, 2048);
        tsplit_kernel<<<dim3(512/32, 2048/32), tb>>>(
            w2 + (size_t)i*DMM*DD, wh + W_W20 + (size_t)i*1048576,
            wl + W_W20 + (size_t)i*1048576, 2048, 512);
    }
    tsplit_kernel<<<dim3(32000/32, 512/32), tb>>>(
        headw, wh + W_HEAD, wl + W_HEAD, 512, 32000);

    embed_kernel<<<(MM*DD)/256, 256>>>(x, tok, pos, h);

    for (int i = 0; i < NLL; i++) {
        // attn block
        layernorm_kernel<<<MM, 256>>>(h, ln1g + i*DD, ln1b + i*DD, xh, xl);
        tcgemm<256><<<dim3(1536/256, MM/128), 256, GS256>>>(
            xh, xl, wh + W_QKV0 + (size_t)i*786432, wl + W_QKV0 + (size_t)i*786432,
            qkvb + (size_t)i*3*DD, nullptr, big, nullptr, nullptr, 512, 1536, 0);
        attn_kernel<<<dim3(LL/ATQ, NHH, BB), 256, ATTN_SMEM>>>(big, xh, xl);
        tcgemm<128><<<dim3(512/128, MM/128), 128, GS128>>>(
            xh, xl, wh + W_OUT0 + (size_t)i*262144, wl + W_OUT0 + (size_t)i*262144,
            outb + (size_t)i*DD, h, h, nullptr, nullptr, 512, 512, 2);
        // mlp block
        layernorm_kernel<<<MM, 256>>>(h, ln2g + i*DD, ln2b + i*DD, xh, xl);
        tcgemm<256><<<dim3(2048/256, MM/128), 256, GS256>>>(
            xh, xl, wh + W_W10 + (size_t)i*1048576, wl + W_W10 + (size_t)i*1048576,
            b1 + (size_t)i*DMM, nullptr, nullptr, mh, ml, 512, 2048, 1);
        tcgemm<128><<<dim3(512/128, MM/128), 128, GS128>>>(
            mh, ml, wh + W_W20 + (size_t)i*1048576, wl + W_W20 + (size_t)i*1048576,
            b2 + (size_t)i*DD, h, h, nullptr, nullptr, 2048, 512, 2);
    }

    layernorm_kernel<<<MM, 256>>>(h, lnfg, lnfb, xh, xl);
    tcgemm<256><<<dim3(VV/256, MM/128), 256, GS256>>>(
        xh, xl, wh + W_HEAD, wl + W_HEAD,
        nullptr, nullptr, out, nullptr, nullptr, 512, VV, 3);
}

// round 12
// speedup vs baseline: 4.1354x; 1.4383x over previous
#include <cuda_runtime.h>
#include <cuda_fp16.h>
#include <math.h>
#include <stdint.h>

typedef __half hf;

// Problem dims
#define BB 2
#define LL 2048
#define DD 512
#define NHH 8
#define NLL 4
#define DMM 2048
#define VV 32000
#define HDD 64
#define MM (BB*LL)          // 4096 rows

// ---------------- PTX helpers ------------------------------------------------
__device__ __forceinline__ uint32_t smem_u32(const void* p) {
    uint32_t a;
    asm("{ .reg .u64 t; cvta.to.shared.u64 t, %1; cvt.u32.u64 %0, t; }"
        : "=r"(a) : "l"(p));
    return a;
}

#define LDSM_X4(r0,r1,r2,r3,addr) \
    asm volatile("ldmatrix.sync.aligned.m8n8.x4.shared.b16 {%0,%1,%2,%3}, [%4];" \
        : "=r"(r0), "=r"(r1), "=r"(r2), "=r"(r3) : "r"(addr))
#define LDSM_X4_T(r0,r1,r2,r3,addr) \
    asm volatile("ldmatrix.sync.aligned.m8n8.x4.trans.shared.b16 {%0,%1,%2,%3}, [%4];" \
        : "=r"(r0), "=r"(r1), "=r"(r2), "=r"(r3) : "r"(addr))
#define MMA16816(d, a, b) \
    asm volatile("mma.sync.aligned.m16n8k16.row.col.f32.f16.f16.f32 " \
        "{%0,%1,%2,%3}, {%4,%5,%6,%7}, {%8,%9}, {%0,%1,%2,%3};" \
        : "+f"((d)[0]), "+f"((d)[1]), "+f"((d)[2]), "+f"((d)[3]) \
        : "r"((a)[0]), "r"((a)[1]), "r"((a)[2]), "r"((a)[3]), \
          "r"((b)[0]), "r"((b)[1]))
#define CP16(dst, src) \
    asm volatile("cp.async.cg.shared.global [%0], [%1], 16;" :: "r"(dst), "l"(src))
#define CP_COMMIT() asm volatile("cp.async.commit_group;" ::: "memory")
#define CP_WAIT1()  asm volatile("cp.async.wait_group 1;" ::: "memory")
#define CP_WAIT0()  asm volatile("cp.async.wait_group 0;" ::: "memory")

// pack two fp32 -> fp16x2 hi word + fp16x2 residual-lo word
__device__ __forceinline__ void split2h(float a, float b, uint32_t &h, uint32_t &l) {
    hf ha = __float2half_rn(a), hb = __float2half_rn(b);
    float ra = a - __half2float(ha);
    float rb = b - __half2float(hb);
    hf la = __float2half_rn(ra), lb = __float2half_rn(rb);
    h = (uint32_t)__half_as_ushort(ha) | ((uint32_t)__half_as_ushort(hb) << 16);
    l = (uint32_t)__half_as_ushort(la) | ((uint32_t)__half_as_ushort(lb) << 16);
}
__device__ __forceinline__ uint32_t pack2h(float a, float b) {
    __half2 p = __floats2half2_rn(a, b);
    return *(uint32_t*)&p;
}

// ---------------- scratch (device globals) -----------------------------------
__device__ float g_h  [MM*DD];        // residual stream
__device__ float g_big[MM*3*DD];      // qkv fp32
__device__ hf    g_xh [MM*DD];        // activation hi (LN out / attn out)
__device__ hf    g_xl [MM*DD];
__device__ hf    g_mh [MM*DMM];       // mlp hidden hi/lo
__device__ hf    g_ml [MM*DMM];

// transposed fp16 weights [N,K]
#define W_QKV0 0
#define W_OUT0 3145728
#define W_W10  4194304
#define W_W20  8388608
#define W_HEAD 12582912
#define WTOT   28966912
__device__ hf g_w[WTOT];

// ---------------- embedding --------------------------------------------------
__global__ void embed_kernel(const int* __restrict__ x,
                             const float* __restrict__ tok,
                             const float* __restrict__ pos,
                             float* __restrict__ h)
{
    int i = blockIdx.x * blockDim.x + threadIdx.x;
    int d  = i & (DD-1);
    int bl = i / DD;
    int l  = bl & (LL-1);
    h[i] = tok[(size_t)x[bl]*DD + d] + pos[l*DD + d];
}

// ---------------- layernorm (writes fp16 hi/lo split directly) ---------------
__global__ __launch_bounds__(256) void layernorm_kernel(
    const float* __restrict__ x, const float* __restrict__ g,
    const float* __restrict__ b, hf* __restrict__ yh, hf* __restrict__ yl)
{
    __shared__ float red[16];
    __shared__ float stats[2];
    int row = blockIdx.x;
    int tid = threadIdx.x;
    const float2* xr = (const float2*)(x + (size_t)row*DD);
    float2 v = xr[tid];
    float s = v.x + v.y;
    float q = v.x*v.x + v.y*v.y;
    #pragma unroll
    for (int o = 16; o; o >>= 1) {
        s += __shfl_down_sync(0xffffffffu, s, o);
        q += __shfl_down_sync(0xffffffffu, q, o);
    }
    int w = tid >> 5;
    if ((tid & 31) == 0) { red[w] = s; red[w+8] = q; }
    __syncthreads();
    if (tid < 32) {
        s = (tid < 8) ? red[tid]   : 0.f;
        q = (tid < 8) ? red[tid+8] : 0.f;
        #pragma unroll
        for (int o = 4; o; o >>= 1) {
            s += __shfl_down_sync(0xffffffffu, s, o);
            q += __shfl_down_sync(0xffffffffu, q, o);
        }
        if (tid == 0) {
            float mu  = s * (1.0f/DD);
            float var = q * (1.0f/DD) - mu*mu;
            stats[0] = mu;
            stats[1] = rsqrtf(var + 1e-5f);
        }
    }
    __syncthreads();
    float mu = stats[0], inv = stats[1];
    float2 gg = ((const float2*)g)[tid];
    float2 bb = ((const float2*)b)[tid];
    float ox = (v.x - mu)*inv*gg.x + bb.x;
    float oy = (v.y - mu)*inv*gg.y + bb.y;
    uint32_t hh, ll;
    split2h(ox, oy, hh, ll);
    *(uint32_t*)(yh + (size_t)row*DD + 2*tid) = hh;
    *(uint32_t*)(yl + (size_t)row*DD + 2*tid) = ll;
}

// ---------------- weight transpose+convert: [K,N] -> [N,K] fp16 --------------
__global__ __launch_bounds__(256) void tconv_kernel(
    const float* __restrict__ in, hf* __restrict__ w, int K, int N)
{
    __shared__ float t[32][33];
    int n0 = blockIdx.x * 32, k0 = blockIdx.y * 32;
    int tx = threadIdx.x, ty = threadIdx.y;
    #pragma unroll
    for (int i = ty; i < 32; i += 8)
        t[i][tx] = in[(size_t)(k0+i)*N + n0 + tx];
    __syncthreads();
    #pragma unroll
    for (int i = ty; i < 32; i += 8)
        w[(size_t)(n0+i)*K + k0 + tx] = __float2half_rn(t[tx][i]);
}

// ---------------- fp16x2 GEMM: C = (Ah+Al) @ B^T, cp.async 2-stage -----------
// CTA tile 128 x BN, warp tile 64x64. Two MMA passes per chunk: AhB + AlB.
// fuse: 0=+bias->f32 C, 1=gelu(+bias)->fp16 hi/lo, 2=+bias+res->f32, 3=plain
#define TSTR 72   // smem row stride in fp16 elems (144B: conflict-free ldmatrix)

template<int BN>
__global__ __launch_bounds__(BN) void tcgemm(
    const hf* __restrict__ Ahp, const hf* __restrict__ Alp,
    const hf* __restrict__ Bp,
    const float* __restrict__ bias, const float* __restrict__ res,
    float* __restrict__ C, hf* __restrict__ Ch, hf* __restrict__ Cl,
    int Kd, int Nd, int fuse)
{
    constexpr int NGRP = BN/64;
    constexpr int NT = BN;
    constexpr int AE = 128*TSTR;
    constexpr int BE = BN*TSTR;
    constexpr int STAGE_B = (2*AE + BE)*2;

    extern __shared__ hf sm[];
    uint32_t smb = smem_u32(sm);

    int tid = threadIdx.x, lane = tid & 31, wid = tid >> 5;
    int m0w = (wid / NGRP) * 64;
    int n0w = (wid % NGRP) * 64;
    int bn0  = blockIdx.x * BN;
    int row0 = blockIdx.y * 128;

    float acc[4][8][4];
    #pragma unroll
    for (int i = 0; i < 4; i++)
        #pragma unroll
        for (int j = 0; j < 8; j++)
            #pragma unroll
            for (int k = 0; k < 4; k++) acc[i][j][k] = 0.f;

    int kseg = Kd >> 6;

    auto load_stage = [&](int buf, int kk) {
        uint32_t sb = smb + buf*STAGE_B;
        #pragma unroll
        for (int p = 0; p < 1024/NT; p++) {
            int id = tid + p*NT; int r = id>>3, cc = (id&7)<<3;
            CP16(sb + (r*TSTR + cc)*2,
                 Ahp + (size_t)(row0+r)*Kd + kk + cc);
        }
        #pragma unroll
        for (int p = 0; p < 1024/NT; p++) {
            int id = tid + p*NT; int r = id>>3, cc = (id&7)<<3;
            CP16(sb + (AE + r*TSTR + cc)*2,
                 Alp + (size_t)(row0+r)*Kd + kk + cc);
        }
        #pragma unroll
        for (int p = 0; p < 8; p++) {
            int id = tid + p*NT; int r = id>>3, cc = (id&7)<<3;
            CP16(sb + (2*AE + r*TSTR + cc)*2,
                 Bp + (size_t)(bn0+r)*Kd + kk + cc);
        }
    };

    load_stage(0, 0);
    CP_COMMIT();

    for (int c = 0; c < kseg; c++) {
        if (c + 1 < kseg) {
            load_stage((c+1)&1, (c+1)<<6);
            CP_COMMIT();
            CP_WAIT1();
        } else {
            CP_WAIT0();
        }
        __syncthreads();

        uint32_t ab  = smb + (c&1)*STAGE_B;
        uint32_t alb = ab + AE*2;
        uint32_t bbb = ab + 2*AE*2;

        #pragma unroll
        for (int ks = 0; ks < 4; ks++) {
            uint32_t ah4[4][4], al4[4][4];
            int aoff = ((m0w + (lane & 15))*TSTR + ks*16 + ((lane >> 4) << 3)) * 2;
            #pragma unroll
            for (int mt = 0; mt < 4; mt++) {
                LDSM_X4(ah4[mt][0],ah4[mt][1],ah4[mt][2],ah4[mt][3],
                        ab  + aoff + mt*16*TSTR*2);
                LDSM_X4(al4[mt][0],al4[mt][1],al4[mt][2],al4[mt][3],
                        alb + aoff + mt*16*TSTR*2);
            }
            int boff = ((n0w + ((lane >> 4) << 3) + (lane & 7))*TSTR +
                        ks*16 + (((lane >> 3) & 1) << 3)) * 2;
            #pragma unroll
            for (int nt2 = 0; nt2 < 4; nt2++) {
                uint32_t b4[4];
                LDSM_X4(b4[0],b4[1],b4[2],b4[3], bbb + boff + nt2*16*TSTR*2);
                uint32_t b01[2]={b4[0],b4[1]}, b23[2]={b4[2],b4[3]};
                #pragma unroll
                for (int mt = 0; mt < 4; mt++) {
                    MMA16816(acc[mt][2*nt2],   ah4[mt], b01);
                    MMA16816(acc[mt][2*nt2+1], ah4[mt], b23);
                }
                #pragma unroll
                for (int mt = 0; mt < 4; mt++) {
                    MMA16816(acc[mt][2*nt2],   al4[mt], b01);
                    MMA16816(acc[mt][2*nt2+1], al4[mt], b23);
                }
            }
        }
        __syncthreads();
    }

    // epilogue
    #pragma unroll
    for (int mt = 0; mt < 4; mt++) {
        int r0 = row0 + m0w + mt*16 + (lane >> 2);
        #pragma unroll
        for (int nt = 0; nt < 8; nt++) {
            int col = bn0 + n0w + nt*8 + ((lane & 3) << 1);
            float2 v0 = make_float2(acc[mt][nt][0], acc[mt][nt][1]);
            float2 v1 = make_float2(acc[mt][nt][2], acc[mt][nt][3]);
            if (fuse != 3) {
                float2 bv = *(const float2*)(bias + col);
                v0.x += bv.x; v0.y += bv.y;
                v1.x += bv.x; v1.y += bv.y;
            }
            if (fuse == 1) {
                v0.x = 0.5f*v0.x*(1.0f + erff(v0.x*0.7071067811865475f));
                v0.y = 0.5f*v0.y*(1.0f + erff(v0.y*0.7071067811865475f));
                v1.x = 0.5f*v1.x*(1.0f + erff(v1.x*0.7071067811865475f));
                v1.y = 0.5f*v1.y*(1.0f + erff(v1.y*0.7071067811865475f));
                uint32_t h0, l0, h1, l1;
                split2h(v0.x, v0.y, h0, l0);
                split2h(v1.x, v1.y, h1, l1);
                *(uint32_t*)(Ch + (size_t)r0*Nd + col)     = h0;
                *(uint32_t*)(Cl + (size_t)r0*Nd + col)     = l0;
                *(uint32_t*)(Ch + (size_t)(r0+8)*Nd + col) = h1;
                *(uint32_t*)(Cl + (size_t)(r0+8)*Nd + col) = l1;
                continue;
            }
            if (fuse == 2) {
                float2 r0v = *(const float2*)(res + (size_t)r0*Nd + col);
                float2 r1v = *(const float2*)(res + (size_t)(r0+8)*Nd + col);
                v0.x += r0v.x; v0.y += r0v.y;
                v1.x += r1v.x; v1.y += r1v.y;
            }
            *(float2*)(C + (size_t)r0*Nd + col)     = v0;
            *(float2*)(C + (size_t)(r0+8)*Nd + col) = v1;
        }
    }
}

#define GS256 147456
#define GS128 110592

// ---------------- tensor-core flash attention (fp16x2) -----------------------
// S = Qh K + Ql K (K single fp16); PV single pass (P fp16).
#define ATQ 128
#define ATK 64
#define SQH 0
#define SQL 9216
#define SK  18432
#define SV  23040
#define ATTN_SMEM (27648*2)

__global__ __launch_bounds__(256, 2) void attn_kernel(
    const float* __restrict__ qkv,
    hf* __restrict__ oh, hf* __restrict__ ol)
{
    extern __shared__ hf smatt[];
    hf* sm = smatt;
    uint32_t smb = smem_u32(sm);

    int q0 = blockIdx.x * ATQ;
    int hh = blockIdx.y;
    int bb = blockIdx.z;
    const float* base = qkv + (size_t)bb * LL * (3*DD);
    int qoff = hh*HDD;
    int koff = DD + hh*HDD;
    int voff = 2*DD + hh*HDD;

    int tid = threadIdx.x, lane = tid & 31, wid = tid >> 5;
    int wrow0 = q0 + wid*16;

    // load Q tile (128x64 fp32 -> fp16 hi/lo)
    #pragma unroll
    for (int p = 0; p < 8; p++) {
        int id = tid + (p << 8);
        int r  = id >> 4;
        int c4 = (id & 15) << 2;
        float4 v = *(const float4*)(base + (size_t)(q0 + r)*(3*DD) + qoff + c4);
        uint32_t h0,l0,h1,l1;
        split2h(v.x, v.y, h0, l0);
        split2h(v.z, v.w, h1, l1);
        *(uint2*)(sm + SQH + r*TSTR + c4) = make_uint2(h0, h1);
        *(uint2*)(sm + SQL + r*TSTR + c4) = make_uint2(l0, l1);
    }

    float Oa[8][4];
    #pragma unroll
    for (int i = 0; i < 8; i++)
        #pragma unroll
        for (int j = 0; j < 4; j++) Oa[i][j] = 0.f;
    float m0 = -1e30f, m1 = -1e30f, l0s = 0.f, l1s = 0.f;

    int qfb = ((wid*16 + (lane & 15))*TSTR + ((lane >> 4) << 3)) * 2;
    int krow = ((lane >> 4) << 3) + (lane & 7);
    int kcol = (((lane >> 3) & 1) << 3);
    int vrow = (((lane >> 3) & 1) << 3) + (lane & 7);
    int vcol = ((lane >> 4) << 3);
    int mr   = lane >> 2;
    int mc2  = (lane & 3) << 1;

    int ntiles = (q0 + ATQ) / ATK;
    for (int t = 0; t < ntiles; t++) {
        int k0 = t * ATK;
        __syncthreads();
        // load K/V tile (64x64 each), fp16
        #pragma unroll
        for (int p = 0; p < 4; p++) {
            int id = tid + (p << 8);
            int r  = id >> 4;
            int c4 = (id & 15) << 2;
            const float* rowp = base + (size_t)(k0 + r)*(3*DD);
            float4 kv = *(const float4*)(rowp + koff + c4);
            float4 vv = *(const float4*)(rowp + voff + c4);
            *(uint2*)(sm + SK + r*TSTR + c4) =
                make_uint2(pack2h(kv.x, kv.y), pack2h(kv.z, kv.w));
            *(uint2*)(sm + SV + r*TSTR + c4) =
                make_uint2(pack2h(vv.x, vv.y), pack2h(vv.z, vv.w));
        }
        __syncthreads();

        if (k0 > wrow0 + 15) continue;

        // ---- S = Qh K + Ql K ----
        float Sa[8][4];
        #pragma unroll
        for (int i = 0; i < 8; i++)
            #pragma unroll
            for (int j = 0; j < 4; j++) Sa[i][j] = 0.f;

        #pragma unroll
        for (int ks = 0; ks < 4; ks++) {
            uint32_t qh[4], ql[4];
            LDSM_X4(qh[0],qh[1],qh[2],qh[3], smb + SQH*2 + qfb + ks*32);
            LDSM_X4(ql[0],ql[1],ql[2],ql[3], smb + SQL*2 + qfb + ks*32);
            #pragma unroll
            for (int np = 0; np < 4; np++) {
                uint32_t kf[4];
                uint32_t ka = smb + ((SK + (np*16 + krow)*TSTR + kcol) * 2) + ks*32;
                LDSM_X4(kf[0],kf[1],kf[2],kf[3], ka);
                uint32_t b01[2] = {kf[0],kf[1]}, b23[2] = {kf[2],kf[3]};
                MMA16816(Sa[2*np],   qh, b01);
                MMA16816(Sa[2*np+1], qh, b23);
                MMA16816(Sa[2*np],   ql, b01);
                MMA16816(Sa[2*np+1], ql, b23);
            }
        }

        // scale + causal mask
        #pragma unroll
        for (int nt = 0; nt < 8; nt++)
            #pragma unroll
            for (int j = 0; j < 4; j++) Sa[nt][j] *= 0.125f;
        if (k0 + 63 > wrow0) {
            int r0g = wrow0 + mr, r1g = r0g + 8;
            #pragma unroll
            for (int nt = 0; nt < 8; nt++) {
                int col = k0 + nt*8 + mc2;
                if (col   > r0g) Sa[nt][0] = -1e30f;
                if (col+1 > r0g) Sa[nt][1] = -1e30f;
                if (col   > r1g) Sa[nt][2] = -1e30f;
                if (col+1 > r1g) Sa[nt][3] = -1e30f;
            }
        }

        // ---- online softmax in registers ----
        float rx0 = -1e30f, rx1 = -1e30f;
        #pragma unroll
        for (int nt = 0; nt < 8; nt++) {
            rx0 = fmaxf(rx0, fmaxf(Sa[nt][0], Sa[nt][1]));
            rx1 = fmaxf(rx1, fmaxf(Sa[nt][2], Sa[nt][3]));
        }
        rx0 = fmaxf(rx0, __shfl_xor_sync(0xffffffffu, rx0, 1));
        rx0 = fmaxf(rx0, __shfl_xor_sync(0xffffffffu, rx0, 2));
        rx1 = fmaxf(rx1, __shfl_xor_sync(0xffffffffu, rx1, 1));
        rx1 = fmaxf(rx1, __shfl_xor_sync(0xffffffffu, rx1, 2));
        float mn0 = fmaxf(m0, rx0), mn1 = fmaxf(m1, rx1);
        float a0 = __expf(m0 - mn0), a1 = __expf(m1 - mn1);
        float s0 = 0.f, s1 = 0.f;
        #pragma unroll
        for (int nt = 0; nt < 8; nt++) {
            Sa[nt][0] = __expf(Sa[nt][0] - mn0);
            Sa[nt][1] = __expf(Sa[nt][1] - mn0);
            Sa[nt][2] = __expf(Sa[nt][2] - mn1);
            Sa[nt][3] = __expf(Sa[nt][3] - mn1);
            s0 += Sa[nt][0] + Sa[nt][1];
            s1 += Sa[nt][2] + Sa[nt][3];
        }
        s0 += __shfl_xor_sync(0xffffffffu, s0, 1);
        s0 += __shfl_xor_sync(0xffffffffu, s0, 2);
        s1 += __shfl_xor_sync(0xffffffffu, s1, 1);
        s1 += __shfl_xor_sync(0xffffffffu, s1, 2);
        l0s = l0s*a0 + s0;  l1s = l1s*a1 + s1;
        m0 = mn0; m1 = mn1;
        #pragma unroll
        for (int nt = 0; nt < 8; nt++) {
            Oa[nt][0] *= a0; Oa[nt][1] *= a0;
            Oa[nt][2] *= a1; Oa[nt][3] *= a1;
        }

        // ---- O += P V (P fp16 single, V fp16 single) ----
        #pragma unroll
        for (int ks = 0; ks < 4; ks++) {
            uint32_t ph[4];
            ph[0] = pack2h(Sa[2*ks][0],   Sa[2*ks][1]);
            ph[1] = pack2h(Sa[2*ks][2],   Sa[2*ks][3]);
            ph[2] = pack2h(Sa[2*ks+1][0], Sa[2*ks+1][1]);
            ph[3] = pack2h(Sa[2*ks+1][2], Sa[2*ks+1][3]);
            #pragma unroll
            for (int np = 0; np < 4; np++) {
                uint32_t vf[4];
                uint32_t va = smb + ((SV + (ks*16 + vrow)*TSTR + np*16 + vcol) * 2);
                LDSM_X4_T(vf[0],vf[1],vf[2],vf[3], va);
                uint32_t b01[2] = {vf[0],vf[1]}, b23[2] = {vf[2],vf[3]};
                MMA16816(Oa[2*np],   ph, b01);
                MMA16816(Oa[2*np+1], ph, b23);
            }
        }
    }

    // ---- write output as fp16 hi/lo ----
    float inv0 = 1.0f / l0s, inv1 = 1.0f / l1s;
    size_t r0g = (size_t)bb*LL + wrow0 + mr;
    size_t r1g = r0g + 8;
    int cb = hh*HDD + mc2;
    #pragma unroll
    for (int nt = 0; nt < 8; nt++) {
        uint32_t h0, l0, h1, l1;
        split2h(Oa[nt][0]*inv0, Oa[nt][1]*inv0, h0, l0);
        split2h(Oa[nt][2]*inv1, Oa[nt][3]*inv1, h1, l1);
        int col = cb + nt*8;
        *(uint32_t*)(oh + r0g*DD + col) = h0;
        *(uint32_t*)(ol + r0g*DD + col) = l0;
        *(uint32_t*)(oh + r1g*DD + col) = h1;
        *(uint32_t*)(ol + r1g*DD + col) = l1;
    }
}

// ---------------- launcher ----------------------------------------------------
extern "C" void kernel_launch(void* const* d_in, const int* in_sizes, int n_in,
                              void* d_out, int out_size)
{
    const int*   x     = (const int*)  d_in[0];
    const float* tok   = (const float*)d_in[1];
    const float* pos   = (const float*)d_in[2];
    const float* ln1g  = (const float*)d_in[3];
    const float* ln1b  = (const float*)d_in[4];
    const float* qkvw  = (const float*)d_in[5];
    const float* qkvb  = (const float*)d_in[6];
    const float* outw  = (const float*)d_in[7];
    const float* outb  = (const float*)d_in[8];
    const float* ln2g  = (const float*)d_in[9];
    const float* ln2b  = (const float*)d_in[10];
    const float* w1    = (const float*)d_in[11];
    const float* b1    = (const float*)d_in[12];
    const float* w2    = (const float*)d_in[13];
    const float* b2    = (const float*)d_in[14];
    const float* lnfg  = (const float*)d_in[15];
    const float* lnfb  = (const float*)d_in[16];
    const float* headw = (const float*)d_in[17];
    float* out = (float*)d_out;

    float *h, *big;
    hf *xh, *xl, *mh, *ml, *w;
    cudaGetSymbolAddress((void**)&h,   g_h);
    cudaGetSymbolAddress((void**)&big, g_big);
    cudaGetSymbolAddress((void**)&xh,  g_xh);
    cudaGetSymbolAddress((void**)&xl,  g_xl);
    cudaGetSymbolAddress((void**)&mh,  g_mh);
    cudaGetSymbolAddress((void**)&ml,  g_ml);
    cudaGetSymbolAddress((void**)&w,   g_w);

    cudaFuncSetAttribute(attn_kernel,
        cudaFuncAttributeMaxDynamicSharedMemorySize, ATTN_SMEM);
    cudaFuncSetAttribute(tcgemm<256>,
        cudaFuncAttributeMaxDynamicSharedMemorySize, GS256);
    cudaFuncSetAttribute(tcgemm<128>,
        cudaFuncAttributeMaxDynamicSharedMemorySize, GS128);

    // weight prep: transpose [K,N] -> [N,K] + fp16 convert
    dim3 tb(32, 8);
    for (int i = 0; i < NLL; i++) {
        tconv_kernel<<<dim3(1536/32, 512/32), tb>>>(
            qkvw + (size_t)i*DD*3*DD, w + W_QKV0 + (size_t)i*786432, 512, 1536);
        tconv_kernel<<<dim3(512/32, 512/32), tb>>>(
            outw + (size_t)i*DD*DD, w + W_OUT0 + (size_t)i*262144, 512, 512);
        tconv_kernel<<<dim3(2048/32, 512/32), tb>>>(
            w1 + (size_t)i*DD*DMM, w + W_W10 + (size_t)i*1048576, 512, 2048);
        tconv_kernel<<<dim3(512/32, 2048/32), tb>>>(
            w2 + (size_t)i*DMM*DD, w + W_W20 + (size_t)i*1048576, 2048, 512);
    }
    tconv_kernel<<<dim3(32000/32, 512/32), tb>>>(
        headw, w + W_HEAD, 512, 32000);

    embed_kernel<<<(MM*DD)/256, 256>>>(x, tok, pos, h);

    for (int i = 0; i < NLL; i++) {
        // attn block
        layernorm_kernel<<<MM, 256>>>(h, ln1g + i*DD, ln1b + i*DD, xh, xl);
        tcgemm<256><<<dim3(1536/256, MM/128), 256, GS256>>>(
            xh, xl, w + W_QKV0 + (size_t)i*786432,
            qkvb + (size_t)i*3*DD, nullptr, big, nullptr, nullptr, 512, 1536, 0);
        attn_kernel<<<dim3(LL/ATQ, NHH, BB), 256, ATTN_SMEM>>>(big, xh, xl);
        tcgemm<128><<<dim3(512/128, MM/128), 128, GS128>>>(
            xh, xl, w + W_OUT0 + (size_t)i*262144,
            outb + (size_t)i*DD, h, h, nullptr, nullptr, 512, 512, 2);
        // mlp block
        layernorm_kernel<<<MM, 256>>>(h, ln2g + i*DD, ln2b + i*DD, xh, xl);
        tcgemm<256><<<dim3(2048/256, MM/128), 256, GS256>>>(
            xh, xl, w + W_W10 + (size_t)i*1048576,
            b1 + (size_t)i*DMM, nullptr, nullptr, mh, ml, 512, 2048, 1);
        tcgemm<128><<<dim3(512/128, MM/128), 128, GS128>>>(
            mh, ml, w + W_W20 + (size_t)i*1048576,
            b2 + (size_t)i*DD, h, h, nullptr, nullptr, 2048, 512, 2);
    }

    layernorm_kernel<<<MM, 256>>>(h, lnfg, lnfb, xh, xl);
    tcgemm<256><<<dim3(VV/256, MM/128), 256, GS256>>>(
        xh, xl, w + W_HEAD,
        nullptr, nullptr, out, nullptr, nullptr, 512, VV, 3);
}